// round 15
// baseline (speedup 1.0000x reference)
#include <cuda_runtime.h>
#include <cuda_fp16.h>
#include <math.h>
#include <stdint.h>

// Problem constants
#define Ed 1024
#define Nd 16
#define Kd 4
#define Rd 64
#define Bd 2
#define Ld 2048
#define Pd 96          // R + 2N
#define CLs 16         // chunk length for scan
#define NCH 128        // L / CLs
#define Md (Bd * Ld)   // 4096 tokens

// ---------------- scratch (static device memory; no allocation) ----------------
__device__ __align__(128) float g_C[(size_t)Md * Nd];        // compact C_proj
__device__ __align__(128) __half g_dt16[(size_t)Md * Ed];
// carry arrays TRANSPOSED: [b][c][n][e] for coalesced access
__device__ __align__(128) float g_hend[(size_t)Bd * NCH * Nd * Ed];
__device__ __align__(128) float g_P[(size_t)Bd * NCH * Nd * Ed];
__device__ __align__(128) float g_hcarry[(size_t)Bd * NCH * Nd * Ed];

// fp16 planes
__device__ __align__(128) __half s_xh[(size_t)Md * Ed];
__device__ __align__(128) __half s_zh[(size_t)Md * Ed];    // silu(z), fp16
__device__ __align__(128) __half s_uh[(size_t)Md * Ed];
__device__ __align__(128) __half s_gh[(size_t)Md * Ed];
__device__ __align__(128) __half s_ph[(size_t)Md * Pd];
__device__ __align__(128) __half s_wzh[(size_t)Ed * Ed];
__device__ __align__(128) __half s_wph[(size_t)Pd * Ed];
__device__ __align__(128) __half s_wdh[(size_t)Ed * Rd];
__device__ __align__(128) __half s_woh[(size_t)Ed * Ed];

// fast-math activations: error ~2e-6, linear pass-through (no cancellation).
__device__ __forceinline__ float softplus_f(float v) {
    return v > 20.f ? v : log1pf(__expf(v));
}
__device__ __forceinline__ float silu_f(float v) {
    return v / (1.f + __expf(-v));
}
__device__ __forceinline__ float expm1_small(float y) {
    if (y > -0.0625f) {
        return y * (1.f + y * (0.5f + y * (0.16666667f + y * 0.041666667f)));
    }
    return expf(y) - 1.f;
}
// e_j = q^{j+1}-1 for j=0..15, log-depth, cancellation-free.
__device__ __forceinline__ void pow_chain16(float em1, float q, float* ej) {
    ej[0] = em1;
    ej[1] = fmaf(em1, q, em1);
    ej[2] = fmaf(ej[1], q, em1);
    ej[3] = fmaf(ej[2], q, em1);
    const float q4 = 1.f + ej[3];
    ej[4] = fmaf(ej[0], q4, ej[3]);
    ej[5] = fmaf(ej[1], q4, ej[3]);
    ej[6] = fmaf(ej[2], q4, ej[3]);
    ej[7] = fmaf(ej[3], q4, ej[3]);
    const float q8 = 1.f + ej[7];
#pragma unroll
    for (int j = 0; j < 8; ++j)
        ej[8 + j] = fmaf(ej[j], q8, ej[7]);
}

// ---------------- single merged fp32 -> fp16 cast over all 5 tensors ----------------
#define CN0 (Md * Ed / 4)
#define CN1 (Ed * Ed / 4)
#define CN2 (Pd * Ed / 4)
#define CN3 (Ed * Rd / 4)
#define CN4 (Ed * Ed / 4)
#define CNT (CN0 + CN1 + CN2 + CN3 + CN4)

__global__ __launch_bounds__(256)
void cast_all_kernel(const float* __restrict__ x,  const float* __restrict__ wz,
                     const float* __restrict__ wp, const float* __restrict__ wdt,
                     const float* __restrict__ wo)
{
    int j = blockIdx.x * 256 + threadIdx.x;
    const float* in; __half* out;
    if (j < CN0)              { in = x;   out = s_xh;  }
    else if ((j -= CN0) < CN1){ in = wz;  out = s_wzh; }
    else if ((j -= CN1) < CN2){ in = wp;  out = s_wph; }
    else if ((j -= CN2) < CN3){ in = wdt; out = s_wdh; }
    else if ((j -= CN3) < CN4){ in = wo;  out = s_woh; }
    else return;
    const float4 v = reinterpret_cast<const float4*>(in)[j];
    reinterpret_cast<__half2*>(out)[j * 2 + 0] = __floats2half2_rn(v.x, v.y);
    reinterpret_cast<__half2*>(out)[j * 2 + 1] = __floats2half2_rn(v.z, v.w);
}

// ================= fp16 GEMM: Y[M,n] = A[M,K] @ W[N,K]^T =================
#define TSTR2 72
#define PLN (128 * TSTR2 * 2)
#define STG (2 * PLN)
#define GSM (3 * STG)

__device__ __forceinline__ void cp16(uint32_t sdst, const void* gsrc, int nbytes) {
    asm volatile("cp.async.cg.shared.global [%0], [%1], 16, %2;"
                 :: "r"(sdst), "l"(gsrc), "r"(nbytes));
}
__device__ __forceinline__ void ldm_x4(uint32_t a, uint32_t& r0, uint32_t& r1,
                                       uint32_t& r2, uint32_t& r3) {
    asm volatile("ldmatrix.sync.aligned.m8n8.x4.shared.b16 {%0,%1,%2,%3}, [%4];"
                 : "=r"(r0), "=r"(r1), "=r"(r2), "=r"(r3) : "r"(a));
}
__device__ __forceinline__ void ldm_x2(uint32_t a, uint32_t& r0, uint32_t& r1) {
    asm volatile("ldmatrix.sync.aligned.m8n8.x2.shared.b16 {%0,%1}, [%2];"
                 : "=r"(r0), "=r"(r1) : "r"(a));
}
__device__ __forceinline__ void mma_f16(float* d, const uint32_t* a, const uint32_t* b) {
    asm volatile(
        "mma.sync.aligned.m16n8k16.row.col.f32.f16.f16.f32 "
        "{%0,%1,%2,%3}, {%4,%5,%6,%7}, {%8,%9}, {%0,%1,%2,%3};"
        : "+f"(d[0]), "+f"(d[1]), "+f"(d[2]), "+f"(d[3])
        : "r"(a[0]), "r"(a[1]), "r"(a[2]), "r"(a[3]), "r"(b[0]), "r"(b[1]));
}

__device__ __forceinline__ void ldp64(uint32_t sdst, const __half* src, int ld,
                                      int row0, int k0, int rows_valid)
{
    const int tid = threadIdx.x;
#pragma unroll
    for (int it = 0; it < 4; ++it) {
        const int slot = tid + (it << 8);
        const int row = slot >> 3;
        const int kg = slot & 7;
        const int rv = (row < rows_valid);
        cp16(sdst + (uint32_t)(row * TSTR2 + kg * 8) * 2,
             src + (size_t)(row0 + (rv ? row : 0)) * ld + k0 + kg * 8,
             rv ? 16 : 0);
    }
}

__device__ __forceinline__ void gemm_core(
    uint32_t sb, const __half* __restrict__ Ah, int lda,
    const __half* __restrict__ Bh, int ldb, int nvB, int Ktot,
    int bm, int bn, float acc[4][4][4])
{
    const int tid = threadIdx.x, wid = tid >> 5, lane = tid & 31;
    const int wm = wid & 1, wn = wid >> 1;
    const int NKT = Ktot >> 6;

    ldp64(sb + 0 * STG + 0 * PLN, Ah, lda, bm, 0, 128);
    ldp64(sb + 0 * STG + 1 * PLN, Bh, ldb, bn, 0, nvB);
    asm volatile("cp.async.commit_group;" ::: "memory");
    if (NKT > 1) {
        ldp64(sb + 1 * STG + 0 * PLN, Ah, lda, bm, 64, 128);
        ldp64(sb + 1 * STG + 1 * PLN, Bh, ldb, bn, 64, nvB);
    }
    asm volatile("cp.async.commit_group;" ::: "memory");

    const int lr = lane & 7;
    const int ag1 = (lane >> 3) & 1;
    const int ag2 = (lane >> 4) & 1;
    const int bg1 = (lane >> 3) & 1;

    int cur = 0, pf = 2;
    for (int kt = 0; kt < NKT; ++kt) {
        asm volatile("cp.async.wait_group 1;" ::: "memory");
        __syncthreads();
        if (kt + 2 < NKT) {
            const uint32_t st2 = sb + (uint32_t)pf * STG;
            const int k0 = (kt + 2) << 6;
            ldp64(st2 + 0 * PLN, Ah, lda, bm, k0, 128);
            ldp64(st2 + 1 * PLN, Bh, ldb, bn, k0, nvB);
        }
        asm volatile("cp.async.commit_group;" ::: "memory");

        const uint32_t st = sb + (uint32_t)cur * STG;
#pragma unroll
        for (int ks = 0; ks < 4; ++ks) {
            uint32_t ah[4][4], bh[4][2];
#pragma unroll
            for (int mi = 0; mi < 4; ++mi) {
                const uint32_t off = (uint32_t)((wm * 64 + mi * 16 + ag1 * 8 + lr) * TSTR2
                                                + ks * 16 + ag2 * 8) * 2;
                ldm_x4(st + 0 * PLN + off, ah[mi][0], ah[mi][1], ah[mi][2], ah[mi][3]);
            }
#pragma unroll
            for (int ni = 0; ni < 4; ++ni) {
                const uint32_t off = (uint32_t)((wn * 32 + ni * 8 + lr) * TSTR2
                                                + ks * 16 + bg1 * 8) * 2;
                ldm_x2(st + 1 * PLN + off, bh[ni][0], bh[ni][1]);
            }
#pragma unroll
            for (int mi = 0; mi < 4; ++mi)
#pragma unroll
                for (int ni = 0; ni < 4; ++ni)
                    mma_f16(acc[mi][ni], ah[mi], bh[ni]);
        }
        cur = (cur == 2) ? 0 : cur + 1;
        pf  = (pf  == 2) ? 0 : pf  + 1;
    }
    asm volatile("cp.async.wait_group 0;" ::: "memory");
}

// merged z + params GEMM; z epilogue applies silu before fp16 store
__global__ __launch_bounds__(256, 2)
void gemm_zp(const __half* __restrict__ xh,
             const __half* __restrict__ wzh, const __half* __restrict__ wph,
             __half* __restrict__ zh, float* __restrict__ Cc,
             __half* __restrict__ ph)
{
    extern __shared__ char smem[];
    const uint32_t sb = (uint32_t)__cvta_generic_to_shared(smem);
    const int tid = threadIdx.x, wid = tid >> 5, lane = tid & 31;
    const int wm = wid & 1, wn = wid >> 1;
    const int bx = blockIdx.x, bm = blockIdx.y * 128;

    float acc[4][4][4];
#pragma unroll
    for (int i = 0; i < 4; ++i)
#pragma unroll
        for (int j = 0; j < 4; ++j)
#pragma unroll
            for (int k = 0; k < 4; ++k) acc[i][j][k] = 0.f;

    if (bx < 8) {
        gemm_core(sb, xh, Ed, wzh, Ed, 128, Ed, bm, bx * 128, acc);
#pragma unroll
        for (int mi = 0; mi < 4; ++mi) {
            const int row = bm + wm * 64 + mi * 16 + (lane >> 2);
#pragma unroll
            for (int ni = 0; ni < 4; ++ni) {
                const int col = bx * 128 + wn * 32 + ni * 8 + (lane & 3) * 2;
                __half2 h01, h23;
                h01.x = __float2half_rn(silu_f(acc[mi][ni][0]));
                h01.y = __float2half_rn(silu_f(acc[mi][ni][1]));
                h23.x = __float2half_rn(silu_f(acc[mi][ni][2]));
                h23.y = __float2half_rn(silu_f(acc[mi][ni][3]));
                *reinterpret_cast<__half2*>(&zh[(size_t)row * Ed + col]) = h01;
                *reinterpret_cast<__half2*>(&zh[(size_t)(row + 8) * Ed + col]) = h23;
            }
        }
    } else {
        gemm_core(sb, xh, Ed, wph, Ed, Pd, Ed, bm, 0, acc);
#pragma unroll
        for (int mi = 0; mi < 4; ++mi) {
            const int r0 = bm + wm * 64 + mi * 16 + (lane >> 2);
#pragma unroll
            for (int ni = 0; ni < 4; ++ni) {
                const int col = wn * 32 + ni * 8 + (lane & 3) * 2;
#pragma unroll
                for (int hh = 0; hh < 2; ++hh) {
                    const int row = r0 + hh * 8;
                    const float v0 = acc[mi][ni][hh * 2 + 0];
                    const float v1 = acc[mi][ni][hh * 2 + 1];
                    if (col < Rd) {
                        __half2 hv; hv.x = __float2half_rn(v0); hv.y = __float2half_rn(v1);
                        *reinterpret_cast<__half2*>(&ph[(size_t)row * Pd + col]) = hv;
                    } else if (col >= Rd + Nd && col < Pd) {
                        *reinterpret_cast<float2*>(&Cc[(size_t)row * Nd + (col - Rd - Nd)]) =
                            make_float2(v0, v1);
                    }
                }
            }
        }
    }
}

// generic GEMM. EPI 0: fp32 out. EPI 1: softplus(acc + bias) -> fp16 out.
template <int EPI>
__global__ __launch_bounds__(256, 2)
void gemm_gen(const __half* __restrict__ Ah, int lda,
              const __half* __restrict__ Bh, int ldb,
              void* __restrict__ Yv, int ldy, int Ktot,
              const float* __restrict__ bias)
{
    extern __shared__ char smem[];
    const uint32_t sb = (uint32_t)__cvta_generic_to_shared(smem);
    const int tid = threadIdx.x, wid = tid >> 5, lane = tid & 31;
    const int wm = wid & 1, wn = wid >> 1;
    const int bm = blockIdx.y * 128, bn = blockIdx.x * 128;

    float acc[4][4][4];
#pragma unroll
    for (int i = 0; i < 4; ++i)
#pragma unroll
        for (int j = 0; j < 4; ++j)
#pragma unroll
            for (int k = 0; k < 4; ++k) acc[i][j][k] = 0.f;

    gemm_core(sb, Ah, lda, Bh, ldb, 128, Ktot, bm, bn, acc);

#pragma unroll
    for (int mi = 0; mi < 4; ++mi) {
        const int row = bm + wm * 64 + mi * 16 + (lane >> 2);
#pragma unroll
        for (int ni = 0; ni < 4; ++ni) {
            const int col = bn + wn * 32 + ni * 8 + (lane & 3) * 2;
            if (EPI == 0) {
                float* Y = (float*)Yv;
                *reinterpret_cast<float2*>(&Y[(size_t)row * ldy + col]) =
                    make_float2(acc[mi][ni][0], acc[mi][ni][1]);
                *reinterpret_cast<float2*>(&Y[(size_t)(row + 8) * ldy + col]) =
                    make_float2(acc[mi][ni][2], acc[mi][ni][3]);
            } else {
                __half* Y = (__half*)Yv;
                const float b0 = bias[col], b1 = bias[col + 1];
                __half2 h01, h23;
                h01.x = __float2half_rn(softplus_f(acc[mi][ni][0] + b0));
                h01.y = __float2half_rn(softplus_f(acc[mi][ni][1] + b1));
                h23.x = __float2half_rn(softplus_f(acc[mi][ni][2] + b0));
                h23.y = __float2half_rn(softplus_f(acc[mi][ni][3] + b1));
                *reinterpret_cast<__half2*>(&Y[(size_t)row * ldy + col]) = h01;
                *reinterpret_cast<__half2*>(&Y[(size_t)(row + 8) * ldy + col]) = h23;
            }
        }
    }
}

// ---------------- generic (non-ratio) fallback paths, noinline ---------------------
__device__ __noinline__ void scanA_generic(const float* A_log, const float* x,
                                           const float* cw, int e, int c, int b)
{
    float A[Nd], invA[Nd];
    bool sm[Nd];
    for (int j = 0; j < Nd; ++j) {
        A[j] = -expf(A_log[(size_t)e * Nd + j]);
        invA[j] = 1.f / (A[j] + 1e-10f);
        sm[j] = fabsf(A[j]) < 1e-5f;
    }
    float h[Nd];
    for (int j = 0; j < Nd; ++j) h[j] = 0.f;
    float S = 0.f;
    const size_t rowbase = (size_t)b * Ld * Ed + e;
    const int l0 = c * CLs;
    const int lprev = (c > 0) ? (l0 - 1) : l0;
    const float4 wcv = *reinterpret_cast<const float4*>(&cw[(size_t)e * Kd]);
    float x0, x1, x2, x3;
    {
        int l = lprev - 3;
        x0 = (l >= 0) ? x[rowbase + (size_t)l * Ed] : 0.f; ++l;
        x1 = (l >= 0) ? x[rowbase + (size_t)l * Ed] : 0.f; ++l;
        x2 = (l >= 0) ? x[rowbase + (size_t)l * Ed] : 0.f; ++l;
        x3 = x[rowbase + (size_t)l * Ed];
    }
    float pu = __half2float(__float2half_rn(
        silu_f(wcv.x * x0 + wcv.y * x1 + wcv.z * x2 + wcv.w * x3)));
    float pd = __half2float(g_dt16[rowbase + (size_t)lprev * Ed]);
    for (int t = 0; t < CLs; ++t) {
        S += pd;
        for (int j = 0; j < Nd; ++j) {
            const float em1 = expm1_small(pd * A[j]);
            const float a = 1.f + em1;
            const float bt = sm[j] ? pd : em1 * invA[j];
            h[j] = fmaf(a, h[j], bt * pu);
        }
        const int lcur = l0 + t;
        float ucur;
        if (c == 0 && t == 0) {
            ucur = pu;
        } else {
            x0 = x1; x1 = x2; x2 = x3;
            x3 = x[rowbase + (size_t)lcur * Ed];
            ucur = __half2float(__float2half_rn(
                silu_f(wcv.x * x0 + wcv.y * x1 + wcv.z * x2 + wcv.w * x3)));
        }
        s_uh[rowbase + (size_t)lcur * Ed] = __float2half_rn(ucur);
        pd = __half2float(g_dt16[rowbase + (size_t)lcur * Ed]);
        pu = ucur;
    }
    const size_t ho = ((size_t)(b * NCH + c) * Nd) * Ed + e;
    for (int j = 0; j < Nd; ++j) {
        g_hend[ho + (size_t)j * Ed] = h[j];
        g_P[ho + (size_t)j * Ed] = expf(S * A[j]);
    }
}

__device__ __noinline__ void scanC_generic(const float* A_log, float dve,
                                           const float (*Cs)[Nd], int e, int c, int b)
{
    float A[Nd], invA[Nd];
    bool sm[Nd];
    for (int j = 0; j < Nd; ++j) {
        A[j] = -expf(A_log[(size_t)e * Nd + j]);
        invA[j] = 1.f / (A[j] + 1e-10f);
        sm[j] = fabsf(A[j]) < 1e-5f;
    }
    float h[Nd];
    const size_t ho = ((size_t)(b * NCH + c) * Nd) * Ed + e;
    for (int j = 0; j < Nd; ++j) h[j] = g_hcarry[ho + (size_t)j * Ed];
    const size_t base = ((size_t)b * Ld + (size_t)c * CLs) * Ed + e;
    const size_t pidx = (c > 0) ? (base - Ed) : base;
    float pd = __half2float(g_dt16[pidx]);
    float pu = __half2float(s_uh[pidx]);
    for (int t = 0; t < CLs; ++t) {
        float y = 0.f;
        for (int j = 0; j < Nd; ++j) {
            const float em1 = expm1_small(pd * A[j]);
            const float a = 1.f + em1;
            const float bt = sm[j] ? pd : em1 * invA[j];
            h[j] = fmaf(a, h[j], bt * pu);
            y = fmaf(Cs[t][j], h[j], y);
        }
        const float d_cur = __half2float(g_dt16[base + (size_t)t * Ed]);
        const float u_cur = __half2float(s_uh[base + (size_t)t * Ed]);
        const float zs_cur = __half2float(s_zh[base + (size_t)t * Ed]);   // silu(z)
        const float ys = fmaf(u_cur, dve, y);
        s_gh[base + (size_t)t * Ed] = __float2half_rn(ys * zs_cur);
        pd = d_cur;
        pu = u_cur;
    }
}

// check A[j] == (j+1)*A0 within tolerance (no invA output)
__device__ __forceinline__ bool ratio_check(const float* A_log, int e, float& A0)
{
    bool ok = true;
#pragma unroll
    for (int j = 0; j < Nd; ++j) {
        const float Aj = -expf(A_log[(size_t)e * Nd + j]);
        if (j == 0) A0 = Aj;
        ok = ok && (fabsf(Aj - (float)(j + 1) * A0)
                    <= 1e-5f * (float)(j + 1) * fabsf(A0));
    }
    return ok && (fabsf(A0) > 1e-3f);
}

// ---------------- scan phase A: SMEM-staged fused conv + local scan ----------------
__global__ __launch_bounds__(128, 8)
void scan_phaseA(const float* __restrict__ A_log,
                 const float* __restrict__ x, const float* __restrict__ cw)
{
    __shared__ __align__(16) float  xs[(CLs + 4) * 128];   // rows l0-4 .. l0+CLs-1
    __shared__ __align__(16) __half dts[(CLs + 1) * 128];  // rows l0-1 .. l0+CLs-1

    const int tid = threadIdx.x;
    const int e0 = blockIdx.x * 128;
    const int e = e0 + tid;
    const int c = blockIdx.y, b = blockIdx.z;
    const int l0 = c * CLs;

    {
        const uint32_t sx = (uint32_t)__cvta_generic_to_shared(xs);
        const float* xb = x + (size_t)b * Ld * Ed + e0;
        // (CLs+4)=20 rows x 128 fp32 = 640 x 16B chunks -> 5 per thread
#pragma unroll
        for (int it = 0; it < 5; ++it) {
            const int q = tid + it * 128;
            const int row = q >> 5, cir = q & 31;
            const int g = l0 - 4 + row;
            const int gc = (g >= 0) ? g : 0;
            cp16(sx + (uint32_t)(row * 512 + cir * 16),
                 xb + (size_t)gc * Ed + cir * 4, (g >= 0) ? 16 : 0);
        }
        const uint32_t sd = (uint32_t)__cvta_generic_to_shared(dts);
        const __half* db = g_dt16 + (size_t)b * Ld * Ed + e0;
        // (CLs+1)=17 rows x 128 fp16 = 272 x 16B chunks
#pragma unroll
        for (int it = 0; it < 3; ++it) {
            const int q = tid + it * 128;
            if (q < (CLs + 1) * 16) {
                const int row = q >> 4, cir = q & 15;
                int g = l0 - 1 + row;
                if (g < 0) g = 0;
                cp16(sd + (uint32_t)(row * 256 + cir * 16),
                     db + (size_t)g * Ed + cir * 8, 16);
            }
        }
        asm volatile("cp.async.commit_group;" ::: "memory");
        asm volatile("cp.async.wait_group 0;" ::: "memory");
        __syncthreads();
    }

    float A0;
    if (!ratio_check(A_log, e, A0)) { scanA_generic(A_log, x, cw, e, c, b); return; }
    const float invA0 = 1.f / A0;

    float h[Nd];
#pragma unroll
    for (int j = 0; j < Nd; ++j) h[j] = 0.f;
    float S = 0.f;

    const float4 wcv = *reinterpret_cast<const float4*>(&cw[(size_t)e * Kd]);
    const int i0 = (c == 0) ? 1 : 0;
    float w0 = xs[(i0 + 0) * 128 + tid];
    float w1 = xs[(i0 + 1) * 128 + tid];
    float w2 = xs[(i0 + 2) * 128 + tid];
    float w3 = xs[(i0 + 3) * 128 + tid];
    float pu = __half2float(__float2half_rn(
        silu_f(wcv.x * w0 + wcv.y * w1 + wcv.z * w2 + wcv.w * w3)));

    const size_t ubase = (size_t)b * Ld * Ed + (size_t)l0 * Ed + e;
    for (int t = 0; t < CLs; ++t) {
        const float pd = __half2float(dts[t * 128 + tid]);
        S += pd;
        const float em1 = expm1_small(pd * A0);
        float ej[Nd];
        pow_chain16(em1, 1.f + em1, ej);
        const float puA = pu * invA0;
#pragma unroll
        for (int j = 0; j < Nd; ++j) {
            const float rj = 1.f / (float)(j + 1);   // compile-time immediate
            const float m = ej[j] * rj;
            const float tt = fmaf(m, puA, h[j]);
            h[j] = fmaf(ej[j], h[j], tt);
        }
        float ucur;
        if (c == 0 && t == 0) {
            ucur = pu;                      // index 0 reused
        } else {
            w0 = w1; w1 = w2; w2 = w3;
            w3 = xs[(t + 4) * 128 + tid];
            ucur = __half2float(__float2half_rn(
                silu_f(wcv.x * w0 + wcv.y * w1 + wcv.z * w2 + wcv.w * w3)));
        }
        s_uh[ubase + (size_t)t * Ed] = __float2half_rn(ucur);
        pu = ucur;
    }
    const size_t ho = ((size_t)(b * NCH + c) * Nd) * Ed + e;
    const float Q = expf(S * A0);
    float Pv = Q;
#pragma unroll
    for (int j = 0; j < Nd; ++j) {
        g_hend[ho + (size_t)j * Ed] = h[j];
        g_P[ho + (size_t)j * Ed] = Pv;
        Pv *= Q;
    }
}

// ---------------- scan phase B: combine chunk carries (coalesced) ------------------
__global__ __launch_bounds__(256)
void scan_phaseB()
{
    const int gid = blockIdx.x * 256 + threadIdx.x;    // 0 .. Bd*Nd*Ed-1
    const int b = gid >> 14;                           // Nd*Ed = 16384
    const int rem = gid & 16383;                       // n*Ed + e
    float h = 0.f;
    size_t idx = ((size_t)b * NCH * Nd) * Ed + rem;
    const size_t stride = (size_t)Nd * Ed;
#pragma unroll 4
    for (int c = 0; c < NCH; ++c) {
        g_hcarry[idx] = h;
        h = fmaf(g_P[idx], h, g_hend[idx]);
        idx += stride;
    }
}

// ---------------- scan phase C: SMEM-staged rescan + y + gate ----------------------
__global__ __launch_bounds__(128, 8)
void scan_phaseC(const float* __restrict__ A_log, const float* __restrict__ Dv)
{
    __shared__ __align__(16) __half dts[(CLs + 1) * 128];
    __shared__ __align__(16) __half us[(CLs + 1) * 128];
    __shared__ __align__(16) __half zs[CLs * 128];     // silu(z) staged
    __shared__ float Cs[CLs][Nd];

    const int tid = threadIdx.x;
    const int e0 = blockIdx.x * 128;
    const int e = e0 + tid;
    const int c = blockIdx.y, b = blockIdx.z;
    const int l0 = c * CLs;
    const size_t tok0 = (size_t)b * Ld + l0;

    {
        const uint32_t sd = (uint32_t)__cvta_generic_to_shared(dts);
        const uint32_t su = (uint32_t)__cvta_generic_to_shared(us);
        const uint32_t sz = (uint32_t)__cvta_generic_to_shared(zs);
        const uint32_t sc = (uint32_t)__cvta_generic_to_shared(Cs);
        const __half* db = g_dt16 + (size_t)b * Ld * Ed + e0;
        const __half* ub = s_uh   + (size_t)b * Ld * Ed + e0;
        const __half* zb = s_zh   + (size_t)b * Ld * Ed + e0;
#pragma unroll
        for (int it = 0; it < 3; ++it) {
            const int q = tid + it * 128;
            if (q < (CLs + 1) * 16) {
                const int row = q >> 4, cir = q & 15;
                int g = l0 - 1 + row;
                if (g < 0) g = 0;
                cp16(sd + (uint32_t)(row * 256 + cir * 16),
                     db + (size_t)g * Ed + cir * 8, 16);
                cp16(su + (uint32_t)(row * 256 + cir * 16),
                     ub + (size_t)g * Ed + cir * 8, 16);
            }
        }
#pragma unroll
        for (int it = 0; it < 2; ++it) {
            const int q = tid + it * 128;            // CLs*16 = 256 chunks
            const int row = q >> 4, cir = q & 15;
            cp16(sz + (uint32_t)(row * 256 + cir * 16),
                 zb + (size_t)(l0 + row) * Ed + cir * 8, 16);
        }
        // C: 16x16 fp32 = 1024B = 64 chunks
        if (tid < CLs * Nd / 4)
            cp16(sc + (uint32_t)(tid * 16), g_C + tok0 * Nd + tid * 4, 16);
        asm volatile("cp.async.commit_group;" ::: "memory");
        asm volatile("cp.async.wait_group 0;" ::: "memory");
        __syncthreads();
    }

    const float dve = Dv[e];
    float A0;
    if (!ratio_check(A_log, e, A0)) { scanC_generic(A_log, dve, Cs, e, c, b); return; }
    const float invA0 = 1.f / A0;

    float h[Nd];
    const size_t ho = ((size_t)(b * NCH + c) * Nd) * Ed + e;
#pragma unroll
    for (int j = 0; j < Nd; ++j) h[j] = g_hcarry[ho + (size_t)j * Ed];

    const size_t gbase = tok0 * Ed + e;
    for (int t = 0; t < CLs; ++t) {
        const float pd = __half2float(dts[t * 128 + tid]);
        const float pu = __half2float(us[t * 128 + tid]);
        const float em1 = expm1_small(pd * A0);
        float ej[Nd];
        pow_chain16(em1, 1.f + em1, ej);
        const float puA = pu * invA0;
        float y0 = 0.f, y1 = 0.f, y2 = 0.f, y3 = 0.f;
#pragma unroll
        for (int j = 0; j < Nd; j += 4) {
            {
                const float rj = 1.f / (float)(j + 1);
                const float m = ej[j] * rj;
                const float tt = fmaf(m, puA, h[j]);
                h[j] = fmaf(ej[j], h[j], tt);
                y0 = fmaf(Cs[t][j], h[j], y0);
            }
            {
                const float rj = 1.f / (float)(j + 2);
                const float m = ej[j + 1] * rj;
                const float tt = fmaf(m, puA, h[j + 1]);
                h[j + 1] = fmaf(ej[j + 1], h[j + 1], tt);
                y1 = fmaf(Cs[t][j + 1], h[j + 1], y1);
            }
            {
                const float rj = 1.f / (float)(j + 3);
                const float m = ej[j + 2] * rj;
                const float tt = fmaf(m, puA, h[j + 2]);
                h[j + 2] = fmaf(ej[j + 2], h[j + 2], tt);
                y2 = fmaf(Cs[t][j + 2], h[j + 2], y2);
            }
            {
                const float rj = 1.f / (float)(j + 4);
                const float m = ej[j + 3] * rj;
                const float tt = fmaf(m, puA, h[j + 3]);
                h[j + 3] = fmaf(ej[j + 3], h[j + 3], tt);
                y3 = fmaf(Cs[t][j + 3], h[j + 3], y3);
            }
        }
        const float y = (y0 + y1) + (y2 + y3);
        const float u_cur = __half2float(us[(t + 1) * 128 + tid]);
        const float zs_cur = __half2float(zs[t * 128 + tid]);   // silu(z) precomputed
        const float ys = fmaf(u_cur, dve, y);
        s_gh[gbase + (size_t)t * Ed] = __float2half_rn(ys * zs_cur);
    }
}

// ---------------- host launcher ----------------
extern "C" void kernel_launch(void* const* d_in, const int* in_sizes, int n_in,
                              void* d_out, int out_size)
{
    const float* x     = (const float*)d_in[0];
    const float* W_z   = (const float*)d_in[1];
    const float* W_p   = (const float*)d_in[2];
    const float* cw    = (const float*)d_in[3];
    const float* W_dt  = (const float*)d_in[4];
    const float* b_dt  = (const float*)d_in[5];
    const float* A_log = (const float*)d_in[6];
    const float* Dv    = (const float*)d_in[7];
    const float* W_o   = (const float*)d_in[8];
    float* out = (float*)d_out;

    float* Cc;
    __half *dt16;
    cudaGetSymbolAddress((void**)&Cc,   g_C);
    cudaGetSymbolAddress((void**)&dt16, g_dt16);

    __half *xh, *zh, *gh, *ph, *wzh, *wph, *wdh, *woh;
    cudaGetSymbolAddress((void**)&xh, s_xh);
    cudaGetSymbolAddress((void**)&zh, s_zh);
    cudaGetSymbolAddress((void**)&gh, s_gh);
    cudaGetSymbolAddress((void**)&ph, s_ph);
    cudaGetSymbolAddress((void**)&wzh, s_wzh);
    cudaGetSymbolAddress((void**)&wph, s_wph);
    cudaGetSymbolAddress((void**)&wdh, s_wdh);
    cudaGetSymbolAddress((void**)&woh, s_woh);

    cudaFuncSetAttribute(gemm_zp,     cudaFuncAttributeMaxDynamicSharedMemorySize, GSM);
    cudaFuncSetAttribute(gemm_gen<0>, cudaFuncAttributeMaxDynamicSharedMemorySize, GSM);
    cudaFuncSetAttribute(gemm_gen<1>, cudaFuncAttributeMaxDynamicSharedMemorySize, GSM);

    dim3 blk(256);

    cast_all_kernel<<<(CNT + 255) / 256, blk>>>(x, W_z, W_p, W_dt, W_o);

    gemm_zp<<<dim3(9, Md / 128), blk, GSM>>>(xh, wzh, wph, zh, Cc, ph);
    gemm_gen<1><<<dim3(Ed / 128, Md / 128), blk, GSM>>>(ph, Pd, wdh, Rd,
                                                        dt16, Ed, Rd, b_dt);
    scan_phaseA<<<dim3(Ed / 128, NCH, Bd), dim3(128)>>>(A_log, x, cw);
    scan_phaseB<<<(Bd * Ed * Nd) / 256, blk>>>();
    scan_phaseC<<<dim3(Ed / 128, NCH, Bd), dim3(128)>>>(A_log, Dv);
    gemm_gen<0><<<dim3(Ed / 128, Md / 128), blk, GSM>>>(gh, Ed, woh, Ed,
                                                        out, Ed, Ed, nullptr);
}

// round 16
// speedup vs baseline: 1.2134x; 1.2134x over previous
#include <cuda_runtime.h>
#include <cuda_fp16.h>
#include <math.h>
#include <stdint.h>

// Problem constants
#define Ed 1024
#define Nd 16
#define Kd 4
#define Rd 64
#define Bd 2
#define Ld 2048
#define Pd 96          // R + 2N
#define CLs 32         // chunk length for scan
#define NCH 64         // L / CLs
#define Md (Bd * Ld)   // 4096 tokens

// ---------------- scratch (static device memory; no allocation) ----------------
__device__ __align__(128) float g_C[(size_t)Md * Nd];        // compact C_proj
__device__ __align__(128) __half g_dt16[(size_t)Md * Ed];
__device__ __align__(128) float g_A0[Ed];                    // per-e A0 (0 = generic)
// carry arrays TRANSPOSED: [b][c][n][e] for coalesced access
__device__ __align__(128) float g_hend[(size_t)Bd * NCH * Nd * Ed];
__device__ __align__(128) float g_P[(size_t)Bd * NCH * Nd * Ed];
__device__ __align__(128) float g_hcarry[(size_t)Bd * NCH * Nd * Ed];

// fp16 planes
__device__ __align__(128) __half s_xh[(size_t)Md * Ed];
__device__ __align__(128) __half s_zh[(size_t)Md * Ed];    // silu(z), fp16
__device__ __align__(128) __half s_uh[(size_t)Md * Ed];
__device__ __align__(128) __half s_gh[(size_t)Md * Ed];
__device__ __align__(128) __half s_ph[(size_t)Md * Pd];
__device__ __align__(128) __half s_wzh[(size_t)Ed * Ed];
__device__ __align__(128) __half s_wph[(size_t)Pd * Ed];
__device__ __align__(128) __half s_wdh[(size_t)Ed * Rd];
__device__ __align__(128) __half s_woh[(size_t)Ed * Ed];

// fast-math activations: error ~2e-6, linear pass-through (no cancellation).
__device__ __forceinline__ float softplus_f(float v) {
    return v > 20.f ? v : log1pf(__expf(v));
}
__device__ __forceinline__ float silu_f(float v) {
    return v / (1.f + __expf(-v));
}
__device__ __forceinline__ float expm1_small(float y) {
    if (y > -0.0625f) {
        return y * (1.f + y * (0.5f + y * (0.16666667f + y * 0.041666667f)));
    }
    return expf(y) - 1.f;
}
// e_j = q^{j+1}-1 for j=0..15, log-depth, cancellation-free.
__device__ __forceinline__ void pow_chain16(float em1, float q, float* ej) {
    ej[0] = em1;
    ej[1] = fmaf(em1, q, em1);
    ej[2] = fmaf(ej[1], q, em1);
    ej[3] = fmaf(ej[2], q, em1);
    const float q4 = 1.f + ej[3];
    ej[4] = fmaf(ej[0], q4, ej[3]);
    ej[5] = fmaf(ej[1], q4, ej[3]);
    ej[6] = fmaf(ej[2], q4, ej[3]);
    ej[7] = fmaf(ej[3], q4, ej[3]);
    const float q8 = 1.f + ej[7];
#pragma unroll
    for (int j = 0; j < 8; ++j)
        ej[8 + j] = fmaf(ej[j], q8, ej[7]);
}

// ---------------- merged cast kernel: 5 tensors + per-e A0 precompute --------------
#define CN0 (Md * Ed / 4)
#define CN1 (Ed * Ed / 4)
#define CN2 (Pd * Ed / 4)
#define CN3 (Ed * Rd / 4)
#define CN4 (Ed * Ed / 4)
#define CNT (CN0 + CN1 + CN2 + CN3 + CN4)
#define CNA (CNT + Ed)

__global__ __launch_bounds__(256)
void cast_all_kernel(const float* __restrict__ x,  const float* __restrict__ wz,
                     const float* __restrict__ wp, const float* __restrict__ wdt,
                     const float* __restrict__ wo, const float* __restrict__ A_log)
{
    int j = blockIdx.x * 256 + threadIdx.x;
    const float* in; __half* out;
    if (j < CN0)              { in = x;   out = s_xh;  }
    else if ((j -= CN0) < CN1){ in = wz;  out = s_wzh; }
    else if ((j -= CN1) < CN2){ in = wp;  out = s_wph; }
    else if ((j -= CN2) < CN3){ in = wdt; out = s_wdh; }
    else if ((j -= CN3) < CN4){ in = wo;  out = s_woh; }
    else if ((j -= CN4) < Ed) {
        // per-channel ratio check: A0 stored, 0.0 = generic fallback
        const int e = j;
        float A0 = 0.f;
        bool ok = true;
        for (int n = 0; n < Nd; ++n) {
            const float An = -expf(A_log[(size_t)e * Nd + n]);
            if (n == 0) A0 = An;
            ok = ok && (fabsf(An - (float)(n + 1) * A0)
                        <= 1e-5f * (float)(n + 1) * fabsf(A0));
        }
        ok = ok && (fabsf(A0) > 1e-3f);
        g_A0[e] = ok ? A0 : 0.f;
        return;
    }
    else return;
    const float4 v = reinterpret_cast<const float4*>(in)[j];
    reinterpret_cast<__half2*>(out)[j * 2 + 0] = __floats2half2_rn(v.x, v.y);
    reinterpret_cast<__half2*>(out)[j * 2 + 1] = __floats2half2_rn(v.z, v.w);
}

// ================= fp16 GEMM: Y[M,n] = A[M,K] @ W[N,K]^T =================
#define TSTR2 72
#define PLN (128 * TSTR2 * 2)
#define STG (2 * PLN)
#define GSM (3 * STG)

__device__ __forceinline__ void cp16(uint32_t sdst, const void* gsrc, int nbytes) {
    asm volatile("cp.async.cg.shared.global [%0], [%1], 16, %2;"
                 :: "r"(sdst), "l"(gsrc), "r"(nbytes));
}
__device__ __forceinline__ void ldm_x4(uint32_t a, uint32_t& r0, uint32_t& r1,
                                       uint32_t& r2, uint32_t& r3) {
    asm volatile("ldmatrix.sync.aligned.m8n8.x4.shared.b16 {%0,%1,%2,%3}, [%4];"
                 : "=r"(r0), "=r"(r1), "=r"(r2), "=r"(r3) : "r"(a));
}
__device__ __forceinline__ void ldm_x2(uint32_t a, uint32_t& r0, uint32_t& r1) {
    asm volatile("ldmatrix.sync.aligned.m8n8.x2.shared.b16 {%0,%1}, [%2];"
                 : "=r"(r0), "=r"(r1) : "r"(a));
}
__device__ __forceinline__ void mma_f16(float* d, const uint32_t* a, const uint32_t* b) {
    asm volatile(
        "mma.sync.aligned.m16n8k16.row.col.f32.f16.f16.f32 "
        "{%0,%1,%2,%3}, {%4,%5,%6,%7}, {%8,%9}, {%0,%1,%2,%3};"
        : "+f"(d[0]), "+f"(d[1]), "+f"(d[2]), "+f"(d[3])
        : "r"(a[0]), "r"(a[1]), "r"(a[2]), "r"(a[3]), "r"(b[0]), "r"(b[1]));
}

__device__ __forceinline__ void ldp64(uint32_t sdst, const __half* src, int ld,
                                      int row0, int k0, int rows_valid)
{
    const int tid = threadIdx.x;
#pragma unroll
    for (int it = 0; it < 4; ++it) {
        const int slot = tid + (it << 8);
        const int row = slot >> 3;
        const int kg = slot & 7;
        const int rv = (row < rows_valid);
        cp16(sdst + (uint32_t)(row * TSTR2 + kg * 8) * 2,
             src + (size_t)(row0 + (rv ? row : 0)) * ld + k0 + kg * 8,
             rv ? 16 : 0);
    }
}

__device__ __forceinline__ void gemm_core(
    uint32_t sb, const __half* __restrict__ Ah, int lda,
    const __half* __restrict__ Bh, int ldb, int nvB, int Ktot,
    int bm, int bn, float acc[4][4][4])
{
    const int tid = threadIdx.x, wid = tid >> 5, lane = tid & 31;
    const int wm = wid & 1, wn = wid >> 1;
    const int NKT = Ktot >> 6;

    ldp64(sb + 0 * STG + 0 * PLN, Ah, lda, bm, 0, 128);
    ldp64(sb + 0 * STG + 1 * PLN, Bh, ldb, bn, 0, nvB);
    asm volatile("cp.async.commit_group;" ::: "memory");
    if (NKT > 1) {
        ldp64(sb + 1 * STG + 0 * PLN, Ah, lda, bm, 64, 128);
        ldp64(sb + 1 * STG + 1 * PLN, Bh, ldb, bn, 64, nvB);
    }
    asm volatile("cp.async.commit_group;" ::: "memory");

    const int lr = lane & 7;
    const int ag1 = (lane >> 3) & 1;
    const int ag2 = (lane >> 4) & 1;
    const int bg1 = (lane >> 3) & 1;

    int cur = 0, pf = 2;
    for (int kt = 0; kt < NKT; ++kt) {
        asm volatile("cp.async.wait_group 1;" ::: "memory");
        __syncthreads();
        if (kt + 2 < NKT) {
            const uint32_t st2 = sb + (uint32_t)pf * STG;
            const int k0 = (kt + 2) << 6;
            ldp64(st2 + 0 * PLN, Ah, lda, bm, k0, 128);
            ldp64(st2 + 1 * PLN, Bh, ldb, bn, k0, nvB);
        }
        asm volatile("cp.async.commit_group;" ::: "memory");

        const uint32_t st = sb + (uint32_t)cur * STG;
#pragma unroll
        for (int ks = 0; ks < 4; ++ks) {
            uint32_t ah[4][4], bh[4][2];
#pragma unroll
            for (int mi = 0; mi < 4; ++mi) {
                const uint32_t off = (uint32_t)((wm * 64 + mi * 16 + ag1 * 8 + lr) * TSTR2
                                                + ks * 16 + ag2 * 8) * 2;
                ldm_x4(st + 0 * PLN + off, ah[mi][0], ah[mi][1], ah[mi][2], ah[mi][3]);
            }
#pragma unroll
            for (int ni = 0; ni < 4; ++ni) {
                const uint32_t off = (uint32_t)((wn * 32 + ni * 8 + lr) * TSTR2
                                                + ks * 16 + bg1 * 8) * 2;
                ldm_x2(st + 1 * PLN + off, bh[ni][0], bh[ni][1]);
            }
#pragma unroll
            for (int mi = 0; mi < 4; ++mi)
#pragma unroll
                for (int ni = 0; ni < 4; ++ni)
                    mma_f16(acc[mi][ni], ah[mi], bh[ni]);
        }
        cur = (cur == 2) ? 0 : cur + 1;
        pf  = (pf  == 2) ? 0 : pf  + 1;
    }
    asm volatile("cp.async.wait_group 0;" ::: "memory");
}

// merged z + params GEMM; z epilogue applies silu before fp16 store
__global__ __launch_bounds__(256, 2)
void gemm_zp(const __half* __restrict__ xh,
             const __half* __restrict__ wzh, const __half* __restrict__ wph,
             __half* __restrict__ zh, float* __restrict__ Cc,
             __half* __restrict__ ph)
{
    extern __shared__ char smem[];
    const uint32_t sb = (uint32_t)__cvta_generic_to_shared(smem);
    const int tid = threadIdx.x, wid = tid >> 5, lane = tid & 31;
    const int wm = wid & 1, wn = wid >> 1;
    const int bx = blockIdx.x, bm = blockIdx.y * 128;

    float acc[4][4][4];
#pragma unroll
    for (int i = 0; i < 4; ++i)
#pragma unroll
        for (int j = 0; j < 4; ++j)
#pragma unroll
            for (int k = 0; k < 4; ++k) acc[i][j][k] = 0.f;

    if (bx < 8) {
        gemm_core(sb, xh, Ed, wzh, Ed, 128, Ed, bm, bx * 128, acc);
#pragma unroll
        for (int mi = 0; mi < 4; ++mi) {
            const int row = bm + wm * 64 + mi * 16 + (lane >> 2);
#pragma unroll
            for (int ni = 0; ni < 4; ++ni) {
                const int col = bx * 128 + wn * 32 + ni * 8 + (lane & 3) * 2;
                __half2 h01, h23;
                h01.x = __float2half_rn(silu_f(acc[mi][ni][0]));
                h01.y = __float2half_rn(silu_f(acc[mi][ni][1]));
                h23.x = __float2half_rn(silu_f(acc[mi][ni][2]));
                h23.y = __float2half_rn(silu_f(acc[mi][ni][3]));
                *reinterpret_cast<__half2*>(&zh[(size_t)row * Ed + col]) = h01;
                *reinterpret_cast<__half2*>(&zh[(size_t)(row + 8) * Ed + col]) = h23;
            }
        }
    } else {
        gemm_core(sb, xh, Ed, wph, Ed, Pd, Ed, bm, 0, acc);
#pragma unroll
        for (int mi = 0; mi < 4; ++mi) {
            const int r0 = bm + wm * 64 + mi * 16 + (lane >> 2);
#pragma unroll
            for (int ni = 0; ni < 4; ++ni) {
                const int col = wn * 32 + ni * 8 + (lane & 3) * 2;
#pragma unroll
                for (int hh = 0; hh < 2; ++hh) {
                    const int row = r0 + hh * 8;
                    const float v0 = acc[mi][ni][hh * 2 + 0];
                    const float v1 = acc[mi][ni][hh * 2 + 1];
                    if (col < Rd) {
                        __half2 hv; hv.x = __float2half_rn(v0); hv.y = __float2half_rn(v1);
                        *reinterpret_cast<__half2*>(&ph[(size_t)row * Pd + col]) = hv;
                    } else if (col >= Rd + Nd && col < Pd) {
                        *reinterpret_cast<float2*>(&Cc[(size_t)row * Nd + (col - Rd - Nd)]) =
                            make_float2(v0, v1);
                    }
                }
            }
        }
    }
}

// generic GEMM. EPI 0: fp32 out. EPI 1: softplus(acc + bias) -> fp16 out.
template <int EPI>
__global__ __launch_bounds__(256, 2)
void gemm_gen(const __half* __restrict__ Ah, int lda,
              const __half* __restrict__ Bh, int ldb,
              void* __restrict__ Yv, int ldy, int Ktot,
              const float* __restrict__ bias)
{
    extern __shared__ char smem[];
    const uint32_t sb = (uint32_t)__cvta_generic_to_shared(smem);
    const int tid = threadIdx.x, wid = tid >> 5, lane = tid & 31;
    const int wm = wid & 1, wn = wid >> 1;
    const int bm = blockIdx.y * 128, bn = blockIdx.x * 128;

    float acc[4][4][4];
#pragma unroll
    for (int i = 0; i < 4; ++i)
#pragma unroll
        for (int j = 0; j < 4; ++j)
#pragma unroll
            for (int k = 0; k < 4; ++k) acc[i][j][k] = 0.f;

    gemm_core(sb, Ah, lda, Bh, ldb, 128, Ktot, bm, bn, acc);

#pragma unroll
    for (int mi = 0; mi < 4; ++mi) {
        const int row = bm + wm * 64 + mi * 16 + (lane >> 2);
#pragma unroll
        for (int ni = 0; ni < 4; ++ni) {
            const int col = bn + wn * 32 + ni * 8 + (lane & 3) * 2;
            if (EPI == 0) {
                float* Y = (float*)Yv;
                *reinterpret_cast<float2*>(&Y[(size_t)row * ldy + col]) =
                    make_float2(acc[mi][ni][0], acc[mi][ni][1]);
                *reinterpret_cast<float2*>(&Y[(size_t)(row + 8) * ldy + col]) =
                    make_float2(acc[mi][ni][2], acc[mi][ni][3]);
            } else {
                __half* Y = (__half*)Yv;
                const float b0 = bias[col], b1 = bias[col + 1];
                __half2 h01, h23;
                h01.x = __float2half_rn(softplus_f(acc[mi][ni][0] + b0));
                h01.y = __float2half_rn(softplus_f(acc[mi][ni][1] + b1));
                h23.x = __float2half_rn(softplus_f(acc[mi][ni][2] + b0));
                h23.y = __float2half_rn(softplus_f(acc[mi][ni][3] + b1));
                *reinterpret_cast<__half2*>(&Y[(size_t)row * ldy + col]) = h01;
                *reinterpret_cast<__half2*>(&Y[(size_t)(row + 8) * ldy + col]) = h23;
            }
        }
    }
}

// ---------------- generic (non-ratio) fallback paths, noinline ---------------------
__device__ __noinline__ void scanA_generic(const float* A_log, const float* x,
                                           const float* cw, int e, int c, int b)
{
    float A[Nd], invA[Nd];
    bool sm[Nd];
    for (int j = 0; j < Nd; ++j) {
        A[j] = -expf(A_log[(size_t)e * Nd + j]);
        invA[j] = 1.f / (A[j] + 1e-10f);
        sm[j] = fabsf(A[j]) < 1e-5f;
    }
    float h[Nd];
    for (int j = 0; j < Nd; ++j) h[j] = 0.f;
    float S = 0.f;
    const size_t rowbase = (size_t)b * Ld * Ed + e;
    const int l0 = c * CLs;
    const int lprev = (c > 0) ? (l0 - 1) : l0;
    const float4 wcv = *reinterpret_cast<const float4*>(&cw[(size_t)e * Kd]);
    float x0, x1, x2, x3;
    {
        int l = lprev - 3;
        x0 = (l >= 0) ? x[rowbase + (size_t)l * Ed] : 0.f; ++l;
        x1 = (l >= 0) ? x[rowbase + (size_t)l * Ed] : 0.f; ++l;
        x2 = (l >= 0) ? x[rowbase + (size_t)l * Ed] : 0.f; ++l;
        x3 = x[rowbase + (size_t)l * Ed];
    }
    float pu = __half2float(__float2half_rn(
        silu_f(wcv.x * x0 + wcv.y * x1 + wcv.z * x2 + wcv.w * x3)));
    float pd = __half2float(g_dt16[rowbase + (size_t)lprev * Ed]);
    for (int t = 0; t < CLs; ++t) {
        S += pd;
        for (int j = 0; j < Nd; ++j) {
            const float em1 = expm1_small(pd * A[j]);
            const float a = 1.f + em1;
            const float bt = sm[j] ? pd : em1 * invA[j];
            h[j] = fmaf(a, h[j], bt * pu);
        }
        const int lcur = l0 + t;
        float ucur;
        if (c == 0 && t == 0) {
            ucur = pu;
        } else {
            x0 = x1; x1 = x2; x2 = x3;
            x3 = x[rowbase + (size_t)lcur * Ed];
            ucur = __half2float(__float2half_rn(
                silu_f(wcv.x * x0 + wcv.y * x1 + wcv.z * x2 + wcv.w * x3)));
        }
        s_uh[rowbase + (size_t)lcur * Ed] = __float2half_rn(ucur);
        pd = __half2float(g_dt16[rowbase + (size_t)lcur * Ed]);
        pu = ucur;
    }
    const size_t ho = ((size_t)(b * NCH + c) * Nd) * Ed + e;
    for (int j = 0; j < Nd; ++j) {
        g_hend[ho + (size_t)j * Ed] = h[j];
        g_P[ho + (size_t)j * Ed] = expf(S * A[j]);
    }
}

__device__ __noinline__ void scanC_generic(const float* A_log, float dve,
                                           const float (*Cs)[Nd], int e, int c, int b)
{
    float A[Nd], invA[Nd];
    bool sm[Nd];
    for (int j = 0; j < Nd; ++j) {
        A[j] = -expf(A_log[(size_t)e * Nd + j]);
        invA[j] = 1.f / (A[j] + 1e-10f);
        sm[j] = fabsf(A[j]) < 1e-5f;
    }
    float h[Nd];
    const size_t ho = ((size_t)(b * NCH + c) * Nd) * Ed + e;
    for (int j = 0; j < Nd; ++j) h[j] = g_hcarry[ho + (size_t)j * Ed];
    const size_t base = ((size_t)b * Ld + (size_t)c * CLs) * Ed + e;
    const size_t pidx = (c > 0) ? (base - Ed) : base;
    float pd = __half2float(g_dt16[pidx]);
    float pu = __half2float(s_uh[pidx]);
    for (int t = 0; t < CLs; ++t) {
        float y = 0.f;
        for (int j = 0; j < Nd; ++j) {
            const float em1 = expm1_small(pd * A[j]);
            const float a = 1.f + em1;
            const float bt = sm[j] ? pd : em1 * invA[j];
            h[j] = fmaf(a, h[j], bt * pu);
            y = fmaf(Cs[t][j], h[j], y);
        }
        const float d_cur = __half2float(g_dt16[base + (size_t)t * Ed]);
        const float u_cur = __half2float(s_uh[base + (size_t)t * Ed]);
        const float zs_cur = __half2float(s_zh[base + (size_t)t * Ed]);   // silu(z)
        const float ys = fmaf(u_cur, dve, y);
        s_gh[base + (size_t)t * Ed] = __float2half_rn(ys * zs_cur);
        pd = d_cur;
        pu = u_cur;
    }
}

// ---------------- scan phase A: SMEM-staged fused conv + local scan ----------------
__global__ __launch_bounds__(128, 8)
void scan_phaseA(const float* __restrict__ A_log,
                 const float* __restrict__ x, const float* __restrict__ cw)
{
    __shared__ __align__(16) float  xs[(CLs + 4) * 128];   // rows l0-4 .. l0+CLs-1
    __shared__ __align__(16) __half dts[(CLs + 1) * 128];  // rows l0-1 .. l0+CLs-1

    const int tid = threadIdx.x;
    const int e0 = blockIdx.x * 128;
    const int e = e0 + tid;
    const int c = blockIdx.y, b = blockIdx.z;
    const int l0 = c * CLs;

    {
        const uint32_t sx = (uint32_t)__cvta_generic_to_shared(xs);
        const float* xb = x + (size_t)b * Ld * Ed + e0;
        // (CLs+4)=36 rows x 128 fp32 = 1152 x 16B chunks -> 9 per thread
#pragma unroll
        for (int it = 0; it < 9; ++it) {
            const int q = tid + it * 128;
            const int row = q >> 5, cir = q & 31;
            const int g = l0 - 4 + row;
            const int gc = (g >= 0) ? g : 0;
            cp16(sx + (uint32_t)(row * 512 + cir * 16),
                 xb + (size_t)gc * Ed + cir * 4, (g >= 0) ? 16 : 0);
        }
        const uint32_t sd = (uint32_t)__cvta_generic_to_shared(dts);
        const __half* db = g_dt16 + (size_t)b * Ld * Ed + e0;
        // (CLs+1)=33 rows x 128 fp16 = 528 x 16B chunks
#pragma unroll
        for (int it = 0; it < 5; ++it) {
            const int q = tid + it * 128;
            if (q < (CLs + 1) * 16) {
                const int row = q >> 4, cir = q & 15;
                int g = l0 - 1 + row;
                if (g < 0) g = 0;
                cp16(sd + (uint32_t)(row * 256 + cir * 16),
                     db + (size_t)g * Ed + cir * 8, 16);
            }
        }
        asm volatile("cp.async.commit_group;" ::: "memory");
        asm volatile("cp.async.wait_group 0;" ::: "memory");
        __syncthreads();
    }

    const float A0 = g_A0[e];
    if (A0 == 0.f) { scanA_generic(A_log, x, cw, e, c, b); return; }
    const float invA0 = 1.f / A0;

    float h[Nd];
#pragma unroll
    for (int j = 0; j < Nd; ++j) h[j] = 0.f;
    float S = 0.f;

    const float4 wcv = *reinterpret_cast<const float4*>(&cw[(size_t)e * Kd]);
    const int i0 = (c == 0) ? 1 : 0;
    float w0 = xs[(i0 + 0) * 128 + tid];
    float w1 = xs[(i0 + 1) * 128 + tid];
    float w2 = xs[(i0 + 2) * 128 + tid];
    float w3 = xs[(i0 + 3) * 128 + tid];
    float pu = __half2float(__float2half_rn(
        silu_f(wcv.x * w0 + wcv.y * w1 + wcv.z * w2 + wcv.w * w3)));

    const size_t ubase = (size_t)b * Ld * Ed + (size_t)l0 * Ed + e;
    for (int t = 0; t < CLs; ++t) {
        const float pd = __half2float(dts[t * 128 + tid]);
        S += pd;
        const float em1 = expm1_small(pd * A0);
        float ej[Nd];
        pow_chain16(em1, 1.f + em1, ej);
        const float puA = pu * invA0;
#pragma unroll
        for (int j = 0; j < Nd; ++j) {
            const float rj = 1.f / (float)(j + 1);   // compile-time immediate
            const float m = ej[j] * rj;
            const float tt = fmaf(m, puA, h[j]);
            h[j] = fmaf(ej[j], h[j], tt);
        }
        float ucur;
        if (c == 0 && t == 0) {
            ucur = pu;                      // index 0 reused
        } else {
            w0 = w1; w1 = w2; w2 = w3;
            w3 = xs[(t + 4) * 128 + tid];
            ucur = __half2float(__float2half_rn(
                silu_f(wcv.x * w0 + wcv.y * w1 + wcv.z * w2 + wcv.w * w3)));
        }
        s_uh[ubase + (size_t)t * Ed] = __float2half_rn(ucur);
        pu = ucur;
    }
    const size_t ho = ((size_t)(b * NCH + c) * Nd) * Ed + e;
    const float Q = __expf(S * A0);
    float Pv = Q;
#pragma unroll
    for (int j = 0; j < Nd; ++j) {
        g_hend[ho + (size_t)j * Ed] = h[j];
        g_P[ho + (size_t)j * Ed] = Pv;
        Pv *= Q;
    }
}

// ---------------- scan phase B: combine chunk carries (coalesced) ------------------
__global__ __launch_bounds__(256)
void scan_phaseB()
{
    const int gid = blockIdx.x * 256 + threadIdx.x;    // 0 .. Bd*Nd*Ed-1
    const int b = gid >> 14;                           // Nd*Ed = 16384
    const int rem = gid & 16383;                       // n*Ed + e
    float h = 0.f;
    size_t idx = ((size_t)b * NCH * Nd) * Ed + rem;
    const size_t stride = (size_t)Nd * Ed;
#pragma unroll 4
    for (int c = 0; c < NCH; ++c) {
        g_hcarry[idx] = h;
        h = fmaf(g_P[idx], h, g_hend[idx]);
        idx += stride;
    }
}

// ---------------- scan phase C: SMEM-staged rescan + y + gate ----------------------
__global__ __launch_bounds__(128, 8)
void scan_phaseC(const float* __restrict__ A_log, const float* __restrict__ Dv)
{
    __shared__ __align__(16) __half dts[(CLs + 1) * 128];
    __shared__ __align__(16) __half us[(CLs + 1) * 128];
    __shared__ __align__(16) __half zs[CLs * 128];     // silu(z) staged
    __shared__ float Cs[CLs][Nd];

    const int tid = threadIdx.x;
    const int e0 = blockIdx.x * 128;
    const int e = e0 + tid;
    const int c = blockIdx.y, b = blockIdx.z;
    const int l0 = c * CLs;
    const size_t tok0 = (size_t)b * Ld + l0;

    {
        const uint32_t sd = (uint32_t)__cvta_generic_to_shared(dts);
        const uint32_t su = (uint32_t)__cvta_generic_to_shared(us);
        const uint32_t sz = (uint32_t)__cvta_generic_to_shared(zs);
        const uint32_t sc = (uint32_t)__cvta_generic_to_shared(Cs);
        const __half* db = g_dt16 + (size_t)b * Ld * Ed + e0;
        const __half* ub = s_uh   + (size_t)b * Ld * Ed + e0;
        const __half* zb = s_zh   + (size_t)b * Ld * Ed + e0;
#pragma unroll
        for (int it = 0; it < 5; ++it) {
            const int q = tid + it * 128;
            if (q < (CLs + 1) * 16) {
                const int row = q >> 4, cir = q & 15;
                int g = l0 - 1 + row;
                if (g < 0) g = 0;
                cp16(sd + (uint32_t)(row * 256 + cir * 16),
                     db + (size_t)g * Ed + cir * 8, 16);
                cp16(su + (uint32_t)(row * 256 + cir * 16),
                     ub + (size_t)g * Ed + cir * 8, 16);
            }
        }
#pragma unroll
        for (int it = 0; it < 4; ++it) {
            const int q = tid + it * 128;            // CLs*16 = 512 chunks
            const int row = q >> 4, cir = q & 15;
            cp16(sz + (uint32_t)(row * 256 + cir * 16),
                 zb + (size_t)(l0 + row) * Ed + cir * 8, 16);
        }
        // C: 32x16 fp32 = 2048B = 128 chunks
        cp16(sc + (uint32_t)(tid * 16), g_C + tok0 * Nd + tid * 4, 16);
        asm volatile("cp.async.commit_group;" ::: "memory");
        asm volatile("cp.async.wait_group 0;" ::: "memory");
        __syncthreads();
    }

    const float dve = Dv[e];
    const float A0 = g_A0[e];
    if (A0 == 0.f) { scanC_generic(A_log, dve, Cs, e, c, b); return; }
    const float invA0 = 1.f / A0;

    float h[Nd];
    const size_t ho = ((size_t)(b * NCH + c) * Nd) * Ed + e;
#pragma unroll
    for (int j = 0; j < Nd; ++j) h[j] = g_hcarry[ho + (size_t)j * Ed];

    const size_t gbase = tok0 * Ed + e;
    for (int t = 0; t < CLs; ++t) {
        const float pd = __half2float(dts[t * 128 + tid]);
        const float pu = __half2float(us[t * 128 + tid]);
        const float em1 = expm1_small(pd * A0);
        float ej[Nd];
        pow_chain16(em1, 1.f + em1, ej);
        const float puA = pu * invA0;
        float y0 = 0.f, y1 = 0.f, y2 = 0.f, y3 = 0.f;
#pragma unroll
        for (int j = 0; j < Nd; j += 4) {
            {
                const float rj = 1.f / (float)(j + 1);
                const float m = ej[j] * rj;
                const float tt = fmaf(m, puA, h[j]);
                h[j] = fmaf(ej[j], h[j], tt);
                y0 = fmaf(Cs[t][j], h[j], y0);
            }
            {
                const float rj = 1.f / (float)(j + 2);
                const float m = ej[j + 1] * rj;
                const float tt = fmaf(m, puA, h[j + 1]);
                h[j + 1] = fmaf(ej[j + 1], h[j + 1], tt);
                y1 = fmaf(Cs[t][j + 1], h[j + 1], y1);
            }
            {
                const float rj = 1.f / (float)(j + 3);
                const float m = ej[j + 2] * rj;
                const float tt = fmaf(m, puA, h[j + 2]);
                h[j + 2] = fmaf(ej[j + 2], h[j + 2], tt);
                y2 = fmaf(Cs[t][j + 2], h[j + 2], y2);
            }
            {
                const float rj = 1.f / (float)(j + 4);
                const float m = ej[j + 3] * rj;
                const float tt = fmaf(m, puA, h[j + 3]);
                h[j + 3] = fmaf(ej[j + 3], h[j + 3], tt);
                y3 = fmaf(Cs[t][j + 3], h[j + 3], y3);
            }
        }
        const float y = (y0 + y1) + (y2 + y3);
        const float u_cur = __half2float(us[(t + 1) * 128 + tid]);
        const float zs_cur = __half2float(zs[t * 128 + tid]);   // silu(z) precomputed
        const float ys = fmaf(u_cur, dve, y);
        s_gh[gbase + (size_t)t * Ed] = __float2half_rn(ys * zs_cur);
    }
}

// ---------------- host launcher ----------------
extern "C" void kernel_launch(void* const* d_in, const int* in_sizes, int n_in,
                              void* d_out, int out_size)
{
    const float* x     = (const float*)d_in[0];
    const float* W_z   = (const float*)d_in[1];
    const float* W_p   = (const float*)d_in[2];
    const float* cw    = (const float*)d_in[3];
    const float* W_dt  = (const float*)d_in[4];
    const float* b_dt  = (const float*)d_in[5];
    const float* A_log = (const float*)d_in[6];
    const float* Dv    = (const float*)d_in[7];
    const float* W_o   = (const float*)d_in[8];
    float* out = (float*)d_out;

    float* Cc;
    __half *dt16;
    cudaGetSymbolAddress((void**)&Cc,   g_C);
    cudaGetSymbolAddress((void**)&dt16, g_dt16);

    __half *xh, *zh, *gh, *ph, *wzh, *wph, *wdh, *woh;
    cudaGetSymbolAddress((void**)&xh, s_xh);
    cudaGetSymbolAddress((void**)&zh, s_zh);
    cudaGetSymbolAddress((void**)&gh, s_gh);
    cudaGetSymbolAddress((void**)&ph, s_ph);
    cudaGetSymbolAddress((void**)&wzh, s_wzh);
    cudaGetSymbolAddress((void**)&wph, s_wph);
    cudaGetSymbolAddress((void**)&wdh, s_wdh);
    cudaGetSymbolAddress((void**)&woh, s_woh);

    cudaFuncSetAttribute(gemm_zp,     cudaFuncAttributeMaxDynamicSharedMemorySize, GSM);
    cudaFuncSetAttribute(gemm_gen<0>, cudaFuncAttributeMaxDynamicSharedMemorySize, GSM);
    cudaFuncSetAttribute(gemm_gen<1>, cudaFuncAttributeMaxDynamicSharedMemorySize, GSM);

    dim3 blk(256);

    cast_all_kernel<<<(CNA + 255) / 256, blk>>>(x, W_z, W_p, W_dt, W_o, A_log);

    gemm_zp<<<dim3(9, Md / 128), blk, GSM>>>(xh, wzh, wph, zh, Cc, ph);
    gemm_gen<1><<<dim3(Ed / 128, Md / 128), blk, GSM>>>(ph, Pd, wdh, Rd,
                                                        dt16, Ed, Rd, b_dt);
    scan_phaseA<<<dim3(Ed / 128, NCH, Bd), dim3(128)>>>(A_log, x, cw);
    scan_phaseB<<<(Bd * Ed * Nd) / 256, blk>>>();
    scan_phaseC<<<dim3(Ed / 128, NCH, Bd), dim3(128)>>>(A_log, Dv);
    gemm_gen<0><<<dim3(Ed / 128, Md / 128), blk, GSM>>>(gh, Ed, woh, Ed,
                                                        out, Ed, Ed, nullptr);
}

// round 17
// speedup vs baseline: 1.2163x; 1.0024x over previous
#include <cuda_runtime.h>
#include <cuda_fp16.h>
#include <math.h>
#include <stdint.h>

// Problem constants
#define Ed 1024
#define Nd 16
#define Kd 4
#define Rd 64
#define Bd 2
#define Ld 2048
#define Pd 96          // R + 2N
#define CLs 32         // chunk length for scan
#define NCH 64         // L / CLs
#define Md (Bd * Ld)   // 4096 tokens

// ---------------- scratch (static device memory; no allocation) ----------------
__device__ __align__(128) float g_C[(size_t)Md * Nd];        // compact C_proj
__device__ __align__(128) __half g_dt16[(size_t)Md * Ed];
__device__ __align__(128) float g_A0[Ed];                    // per-e A0 (0 = generic)
// carry arrays TRANSPOSED: [b][c][n][e] for coalesced access
__device__ __align__(128) float g_hend[(size_t)Bd * NCH * Nd * Ed];
__device__ __align__(128) float g_P[(size_t)Bd * NCH * Nd * Ed];
__device__ __align__(128) float g_hcarry[(size_t)Bd * NCH * Nd * Ed];

// fp16 planes
__device__ __align__(128) __half s_xh[(size_t)Md * Ed];
__device__ __align__(128) __half s_zh[(size_t)Md * Ed];    // silu(z), fp16
__device__ __align__(128) __half s_uh[(size_t)Md * Ed];
__device__ __align__(128) __half s_gh[(size_t)Md * Ed];
__device__ __align__(128) __half s_ph[(size_t)Md * Pd];
__device__ __align__(128) __half s_wzh[(size_t)Ed * Ed];
__device__ __align__(128) __half s_wph[(size_t)Pd * Ed];
__device__ __align__(128) __half s_wdh[(size_t)Ed * Rd];
__device__ __align__(128) __half s_woh[(size_t)Ed * Ed];

// fast-math activations: error ~2e-6, linear pass-through (no cancellation).
__device__ __forceinline__ float softplus_f(float v) {
    return v > 20.f ? v : log1pf(__expf(v));
}
__device__ __forceinline__ float silu_f(float v) {
    return v / (1.f + __expf(-v));
}
__device__ __forceinline__ float expm1_small(float y) {
    if (y > -0.0625f) {
        return y * (1.f + y * (0.5f + y * (0.16666667f + y * 0.041666667f)));
    }
    return expf(y) - 1.f;
}
// e_j = q^{j+1}-1 for j=0..15, log-depth, cancellation-free.
__device__ __forceinline__ void pow_chain16(float em1, float q, float* ej) {
    ej[0] = em1;
    ej[1] = fmaf(em1, q, em1);
    ej[2] = fmaf(ej[1], q, em1);
    ej[3] = fmaf(ej[2], q, em1);
    const float q4 = 1.f + ej[3];
    ej[4] = fmaf(ej[0], q4, ej[3]);
    ej[5] = fmaf(ej[1], q4, ej[3]);
    ej[6] = fmaf(ej[2], q4, ej[3]);
    ej[7] = fmaf(ej[3], q4, ej[3]);
    const float q8 = 1.f + ej[7];
#pragma unroll
    for (int j = 0; j < 8; ++j)
        ej[8 + j] = fmaf(ej[j], q8, ej[7]);
}

// ---------------- merged cast kernel: 5 tensors + per-e A0 precompute --------------
#define CN0 (Md * Ed / 4)
#define CN1 (Ed * Ed / 4)
#define CN2 (Pd * Ed / 4)
#define CN3 (Ed * Rd / 4)
#define CN4 (Ed * Ed / 4)
#define CNT (CN0 + CN1 + CN2 + CN3 + CN4)
#define CNA (CNT + Ed)

__global__ __launch_bounds__(256)
void cast_all_kernel(const float* __restrict__ x,  const float* __restrict__ wz,
                     const float* __restrict__ wp, const float* __restrict__ wdt,
                     const float* __restrict__ wo, const float* __restrict__ A_log)
{
    int j = blockIdx.x * 256 + threadIdx.x;
    const float* in; __half* out;
    if (j < CN0)              { in = x;   out = s_xh;  }
    else if ((j -= CN0) < CN1){ in = wz;  out = s_wzh; }
    else if ((j -= CN1) < CN2){ in = wp;  out = s_wph; }
    else if ((j -= CN2) < CN3){ in = wdt; out = s_wdh; }
    else if ((j -= CN3) < CN4){ in = wo;  out = s_woh; }
    else if ((j -= CN4) < Ed) {
        // per-channel ratio check: A0 stored, 0.0 = generic fallback
        const int e = j;
        float A0 = 0.f;
        bool ok = true;
        for (int n = 0; n < Nd; ++n) {
            const float An = -expf(A_log[(size_t)e * Nd + n]);
            if (n == 0) A0 = An;
            ok = ok && (fabsf(An - (float)(n + 1) * A0)
                        <= 1e-5f * (float)(n + 1) * fabsf(A0));
        }
        ok = ok && (fabsf(A0) > 1e-3f);
        g_A0[e] = ok ? A0 : 0.f;
        return;
    }
    else return;
    const float4 v = reinterpret_cast<const float4*>(in)[j];
    reinterpret_cast<__half2*>(out)[j * 2 + 0] = __floats2half2_rn(v.x, v.y);
    reinterpret_cast<__half2*>(out)[j * 2 + 1] = __floats2half2_rn(v.z, v.w);
}

// ================= fp16 GEMM: Y[M,n] = A[M,K] @ W[N,K]^T =================
#define TSTR2 72
#define PLN (128 * TSTR2 * 2)
#define STG (2 * PLN)
#define GSM (3 * STG)

__device__ __forceinline__ void cp16(uint32_t sdst, const void* gsrc, int nbytes) {
    asm volatile("cp.async.cg.shared.global [%0], [%1], 16, %2;"
                 :: "r"(sdst), "l"(gsrc), "r"(nbytes));
}
__device__ __forceinline__ void ldm_x4(uint32_t a, uint32_t& r0, uint32_t& r1,
                                       uint32_t& r2, uint32_t& r3) {
    asm volatile("ldmatrix.sync.aligned.m8n8.x4.shared.b16 {%0,%1,%2,%3}, [%4];"
                 : "=r"(r0), "=r"(r1), "=r"(r2), "=r"(r3) : "r"(a));
}
__device__ __forceinline__ void ldm_x2(uint32_t a, uint32_t& r0, uint32_t& r1) {
    asm volatile("ldmatrix.sync.aligned.m8n8.x2.shared.b16 {%0,%1}, [%2];"
                 : "=r"(r0), "=r"(r1) : "r"(a));
}
__device__ __forceinline__ void mma_f16(float* d, const uint32_t* a, const uint32_t* b) {
    asm volatile(
        "mma.sync.aligned.m16n8k16.row.col.f32.f16.f16.f32 "
        "{%0,%1,%2,%3}, {%4,%5,%6,%7}, {%8,%9}, {%0,%1,%2,%3};"
        : "+f"(d[0]), "+f"(d[1]), "+f"(d[2]), "+f"(d[3])
        : "r"(a[0]), "r"(a[1]), "r"(a[2]), "r"(a[3]), "r"(b[0]), "r"(b[1]));
}

__device__ __forceinline__ void ldp64(uint32_t sdst, const __half* src, int ld,
                                      int row0, int k0, int rows_valid)
{
    const int tid = threadIdx.x;
#pragma unroll
    for (int it = 0; it < 4; ++it) {
        const int slot = tid + (it << 8);
        const int row = slot >> 3;
        const int kg = slot & 7;
        const int rv = (row < rows_valid);
        cp16(sdst + (uint32_t)(row * TSTR2 + kg * 8) * 2,
             src + (size_t)(row0 + (rv ? row : 0)) * ld + k0 + kg * 8,
             rv ? 16 : 0);
    }
}

__device__ __forceinline__ void gemm_core(
    uint32_t sb, const __half* __restrict__ Ah, int lda,
    const __half* __restrict__ Bh, int ldb, int nvB, int Ktot,
    int bm, int bn, float acc[4][4][4])
{
    const int tid = threadIdx.x, wid = tid >> 5, lane = tid & 31;
    const int wm = wid & 1, wn = wid >> 1;
    const int NKT = Ktot >> 6;

    ldp64(sb + 0 * STG + 0 * PLN, Ah, lda, bm, 0, 128);
    ldp64(sb + 0 * STG + 1 * PLN, Bh, ldb, bn, 0, nvB);
    asm volatile("cp.async.commit_group;" ::: "memory");
    if (NKT > 1) {
        ldp64(sb + 1 * STG + 0 * PLN, Ah, lda, bm, 64, 128);
        ldp64(sb + 1 * STG + 1 * PLN, Bh, ldb, bn, 64, nvB);
    }
    asm volatile("cp.async.commit_group;" ::: "memory");

    const int lr = lane & 7;
    const int ag1 = (lane >> 3) & 1;
    const int ag2 = (lane >> 4) & 1;
    const int bg1 = (lane >> 3) & 1;

    int cur = 0, pf = 2;
    for (int kt = 0; kt < NKT; ++kt) {
        asm volatile("cp.async.wait_group 1;" ::: "memory");
        __syncthreads();
        if (kt + 2 < NKT) {
            const uint32_t st2 = sb + (uint32_t)pf * STG;
            const int k0 = (kt + 2) << 6;
            ldp64(st2 + 0 * PLN, Ah, lda, bm, k0, 128);
            ldp64(st2 + 1 * PLN, Bh, ldb, bn, k0, nvB);
        }
        asm volatile("cp.async.commit_group;" ::: "memory");

        const uint32_t st = sb + (uint32_t)cur * STG;
#pragma unroll
        for (int ks = 0; ks < 4; ++ks) {
            uint32_t ah[4][4], bh[4][2];
#pragma unroll
            for (int mi = 0; mi < 4; ++mi) {
                const uint32_t off = (uint32_t)((wm * 64 + mi * 16 + ag1 * 8 + lr) * TSTR2
                                                + ks * 16 + ag2 * 8) * 2;
                ldm_x4(st + 0 * PLN + off, ah[mi][0], ah[mi][1], ah[mi][2], ah[mi][3]);
            }
#pragma unroll
            for (int ni = 0; ni < 4; ++ni) {
                const uint32_t off = (uint32_t)((wn * 32 + ni * 8 + lr) * TSTR2
                                                + ks * 16 + bg1 * 8) * 2;
                ldm_x2(st + 1 * PLN + off, bh[ni][0], bh[ni][1]);
            }
#pragma unroll
            for (int mi = 0; mi < 4; ++mi)
#pragma unroll
                for (int ni = 0; ni < 4; ++ni)
                    mma_f16(acc[mi][ni], ah[mi], bh[ni]);
        }
        cur = (cur == 2) ? 0 : cur + 1;
        pf  = (pf  == 2) ? 0 : pf  + 1;
    }
    asm volatile("cp.async.wait_group 0;" ::: "memory");
}

// merged z + params GEMM; z epilogue applies silu before fp16 store
__global__ __launch_bounds__(256, 2)
void gemm_zp(const __half* __restrict__ xh,
             const __half* __restrict__ wzh, const __half* __restrict__ wph,
             __half* __restrict__ zh, float* __restrict__ Cc,
             __half* __restrict__ ph)
{
    extern __shared__ char smem[];
    const uint32_t sb = (uint32_t)__cvta_generic_to_shared(smem);
    const int tid = threadIdx.x, wid = tid >> 5, lane = tid & 31;
    const int wm = wid & 1, wn = wid >> 1;
    const int bx = blockIdx.x, bm = blockIdx.y * 128;

    float acc[4][4][4];
#pragma unroll
    for (int i = 0; i < 4; ++i)
#pragma unroll
        for (int j = 0; j < 4; ++j)
#pragma unroll
            for (int k = 0; k < 4; ++k) acc[i][j][k] = 0.f;

    if (bx < 8) {
        gemm_core(sb, xh, Ed, wzh, Ed, 128, Ed, bm, bx * 128, acc);
#pragma unroll
        for (int mi = 0; mi < 4; ++mi) {
            const int row = bm + wm * 64 + mi * 16 + (lane >> 2);
#pragma unroll
            for (int ni = 0; ni < 4; ++ni) {
                const int col = bx * 128 + wn * 32 + ni * 8 + (lane & 3) * 2;
                __half2 h01, h23;
                h01.x = __float2half_rn(silu_f(acc[mi][ni][0]));
                h01.y = __float2half_rn(silu_f(acc[mi][ni][1]));
                h23.x = __float2half_rn(silu_f(acc[mi][ni][2]));
                h23.y = __float2half_rn(silu_f(acc[mi][ni][3]));
                *reinterpret_cast<__half2*>(&zh[(size_t)row * Ed + col]) = h01;
                *reinterpret_cast<__half2*>(&zh[(size_t)(row + 8) * Ed + col]) = h23;
            }
        }
    } else {
        gemm_core(sb, xh, Ed, wph, Ed, Pd, Ed, bm, 0, acc);
#pragma unroll
        for (int mi = 0; mi < 4; ++mi) {
            const int r0 = bm + wm * 64 + mi * 16 + (lane >> 2);
#pragma unroll
            for (int ni = 0; ni < 4; ++ni) {
                const int col = wn * 32 + ni * 8 + (lane & 3) * 2;
#pragma unroll
                for (int hh = 0; hh < 2; ++hh) {
                    const int row = r0 + hh * 8;
                    const float v0 = acc[mi][ni][hh * 2 + 0];
                    const float v1 = acc[mi][ni][hh * 2 + 1];
                    if (col < Rd) {
                        __half2 hv; hv.x = __float2half_rn(v0); hv.y = __float2half_rn(v1);
                        *reinterpret_cast<__half2*>(&ph[(size_t)row * Pd + col]) = hv;
                    } else if (col >= Rd + Nd && col < Pd) {
                        *reinterpret_cast<float2*>(&Cc[(size_t)row * Nd + (col - Rd - Nd)]) =
                            make_float2(v0, v1);
                    }
                }
            }
        }
    }
}

// generic GEMM. EPI 0: fp32 out. EPI 1: softplus(acc + bias) -> fp16 out.
template <int EPI>
__global__ __launch_bounds__(256, 2)
void gemm_gen(const __half* __restrict__ Ah, int lda,
              const __half* __restrict__ Bh, int ldb,
              void* __restrict__ Yv, int ldy, int Ktot,
              const float* __restrict__ bias)
{
    extern __shared__ char smem[];
    const uint32_t sb = (uint32_t)__cvta_generic_to_shared(smem);
    const int tid = threadIdx.x, wid = tid >> 5, lane = tid & 31;
    const int wm = wid & 1, wn = wid >> 1;
    const int bm = blockIdx.y * 128, bn = blockIdx.x * 128;

    float acc[4][4][4];
#pragma unroll
    for (int i = 0; i < 4; ++i)
#pragma unroll
        for (int j = 0; j < 4; ++j)
#pragma unroll
            for (int k = 0; k < 4; ++k) acc[i][j][k] = 0.f;

    gemm_core(sb, Ah, lda, Bh, ldb, 128, Ktot, bm, bn, acc);

#pragma unroll
    for (int mi = 0; mi < 4; ++mi) {
        const int row = bm + wm * 64 + mi * 16 + (lane >> 2);
#pragma unroll
        for (int ni = 0; ni < 4; ++ni) {
            const int col = bn + wn * 32 + ni * 8 + (lane & 3) * 2;
            if (EPI == 0) {
                float* Y = (float*)Yv;
                *reinterpret_cast<float2*>(&Y[(size_t)row * ldy + col]) =
                    make_float2(acc[mi][ni][0], acc[mi][ni][1]);
                *reinterpret_cast<float2*>(&Y[(size_t)(row + 8) * ldy + col]) =
                    make_float2(acc[mi][ni][2], acc[mi][ni][3]);
            } else {
                __half* Y = (__half*)Yv;
                const float b0 = bias[col], b1 = bias[col + 1];
                __half2 h01, h23;
                h01.x = __float2half_rn(softplus_f(acc[mi][ni][0] + b0));
                h01.y = __float2half_rn(softplus_f(acc[mi][ni][1] + b1));
                h23.x = __float2half_rn(softplus_f(acc[mi][ni][2] + b0));
                h23.y = __float2half_rn(softplus_f(acc[mi][ni][3] + b1));
                *reinterpret_cast<__half2*>(&Y[(size_t)row * ldy + col]) = h01;
                *reinterpret_cast<__half2*>(&Y[(size_t)(row + 8) * ldy + col]) = h23;
            }
        }
    }
}

// ---------------- generic (non-ratio) fallback paths, noinline ---------------------
__device__ __noinline__ void scanA_generic(const float* A_log, const float* cw,
                                           int e, int c, int b)
{
    float A[Nd], invA[Nd];
    bool sm[Nd];
    for (int j = 0; j < Nd; ++j) {
        A[j] = -expf(A_log[(size_t)e * Nd + j]);
        invA[j] = 1.f / (A[j] + 1e-10f);
        sm[j] = fabsf(A[j]) < 1e-5f;
    }
    float h[Nd];
    for (int j = 0; j < Nd; ++j) h[j] = 0.f;
    float S = 0.f;
    const size_t rowbase = (size_t)b * Ld * Ed + e;
    const int l0 = c * CLs;
    const int lprev = (c > 0) ? (l0 - 1) : l0;
    const float4 wcv = *reinterpret_cast<const float4*>(&cw[(size_t)e * Kd]);
    float x0, x1, x2, x3;
    {
        int l = lprev - 3;
        x0 = (l >= 0) ? __half2float(s_xh[rowbase + (size_t)l * Ed]) : 0.f; ++l;
        x1 = (l >= 0) ? __half2float(s_xh[rowbase + (size_t)l * Ed]) : 0.f; ++l;
        x2 = (l >= 0) ? __half2float(s_xh[rowbase + (size_t)l * Ed]) : 0.f; ++l;
        x3 = __half2float(s_xh[rowbase + (size_t)l * Ed]);
    }
    float pu = __half2float(__float2half_rn(
        silu_f(wcv.x * x0 + wcv.y * x1 + wcv.z * x2 + wcv.w * x3)));
    float pd = __half2float(g_dt16[rowbase + (size_t)lprev * Ed]);
    for (int t = 0; t < CLs; ++t) {
        S += pd;
        for (int j = 0; j < Nd; ++j) {
            const float em1 = expm1_small(pd * A[j]);
            const float a = 1.f + em1;
            const float bt = sm[j] ? pd : em1 * invA[j];
            h[j] = fmaf(a, h[j], bt * pu);
        }
        const int lcur = l0 + t;
        float ucur;
        if (c == 0 && t == 0) {
            ucur = pu;
        } else {
            x0 = x1; x1 = x2; x2 = x3;
            x3 = __half2float(s_xh[rowbase + (size_t)lcur * Ed]);
            ucur = __half2float(__float2half_rn(
                silu_f(wcv.x * x0 + wcv.y * x1 + wcv.z * x2 + wcv.w * x3)));
        }
        s_uh[rowbase + (size_t)lcur * Ed] = __float2half_rn(ucur);
        pd = __half2float(g_dt16[rowbase + (size_t)lcur * Ed]);
        pu = ucur;
    }
    const size_t ho = ((size_t)(b * NCH + c) * Nd) * Ed + e;
    for (int j = 0; j < Nd; ++j) {
        g_hend[ho + (size_t)j * Ed] = h[j];
        g_P[ho + (size_t)j * Ed] = expf(S * A[j]);
    }
}

__device__ __noinline__ void scanC_generic(const float* A_log, float dve,
                                           const float (*Cs)[Nd], int e, int c, int b)
{
    float A[Nd], invA[Nd];
    bool sm[Nd];
    for (int j = 0; j < Nd; ++j) {
        A[j] = -expf(A_log[(size_t)e * Nd + j]);
        invA[j] = 1.f / (A[j] + 1e-10f);
        sm[j] = fabsf(A[j]) < 1e-5f;
    }
    float h[Nd];
    const size_t ho = ((size_t)(b * NCH + c) * Nd) * Ed + e;
    for (int j = 0; j < Nd; ++j) h[j] = g_hcarry[ho + (size_t)j * Ed];
    const size_t base = ((size_t)b * Ld + (size_t)c * CLs) * Ed + e;
    const size_t pidx = (c > 0) ? (base - Ed) : base;
    float pd = __half2float(g_dt16[pidx]);
    float pu = __half2float(s_uh[pidx]);
    for (int t = 0; t < CLs; ++t) {
        float y = 0.f;
        for (int j = 0; j < Nd; ++j) {
            const float em1 = expm1_small(pd * A[j]);
            const float a = 1.f + em1;
            const float bt = sm[j] ? pd : em1 * invA[j];
            h[j] = fmaf(a, h[j], bt * pu);
            y = fmaf(Cs[t][j], h[j], y);
        }
        const float d_cur = __half2float(g_dt16[base + (size_t)t * Ed]);
        const float u_cur = __half2float(s_uh[base + (size_t)t * Ed]);
        const float zs_cur = __half2float(s_zh[base + (size_t)t * Ed]);   // silu(z)
        const float ys = fmaf(u_cur, dve, y);
        s_gh[base + (size_t)t * Ed] = __float2half_rn(ys * zs_cur);
        pd = d_cur;
        pu = u_cur;
    }
}

// ---------------- scan phase A: SMEM-staged fused conv + local scan ----------------
// x staged from the fp16 plane (s_xh) — half the bytes of fp32 x.
__global__ __launch_bounds__(128, 8)
void scan_phaseA(const float* __restrict__ A_log, const float* __restrict__ cw)
{
    __shared__ __align__(16) __half xs[(CLs + 4) * 128];   // rows l0-4 .. l0+CLs-1
    __shared__ __align__(16) __half dts[(CLs + 1) * 128];  // rows l0-1 .. l0+CLs-1

    const int tid = threadIdx.x;
    const int e0 = blockIdx.x * 128;
    const int e = e0 + tid;
    const int c = blockIdx.y, b = blockIdx.z;
    const int l0 = c * CLs;

    {
        const uint32_t sx = (uint32_t)__cvta_generic_to_shared(xs);
        const __half* xb = s_xh + (size_t)b * Ld * Ed + e0;
        // (CLs+4)=36 rows x 128 fp16 = 576 x 16B chunks
#pragma unroll
        for (int it = 0; it < 5; ++it) {
            const int q = tid + it * 128;
            if (q < (CLs + 4) * 16) {
                const int row = q >> 4, cir = q & 15;
                const int g = l0 - 4 + row;
                const int gc = (g >= 0) ? g : 0;
                cp16(sx + (uint32_t)(row * 256 + cir * 16),
                     xb + (size_t)gc * Ed + cir * 8, (g >= 0) ? 16 : 0);
            }
        }
        const uint32_t sd = (uint32_t)__cvta_generic_to_shared(dts);
        const __half* db = g_dt16 + (size_t)b * Ld * Ed + e0;
        // (CLs+1)=33 rows x 128 fp16 = 528 x 16B chunks
#pragma unroll
        for (int it = 0; it < 5; ++it) {
            const int q = tid + it * 128;
            if (q < (CLs + 1) * 16) {
                const int row = q >> 4, cir = q & 15;
                int g = l0 - 1 + row;
                if (g < 0) g = 0;
                cp16(sd + (uint32_t)(row * 256 + cir * 16),
                     db + (size_t)g * Ed + cir * 8, 16);
            }
        }
        asm volatile("cp.async.commit_group;" ::: "memory");
        asm volatile("cp.async.wait_group 0;" ::: "memory");
        __syncthreads();
    }

    const float A0 = g_A0[e];
    if (A0 == 0.f) { scanA_generic(A_log, cw, e, c, b); return; }
    const float invA0 = 1.f / A0;

    float h[Nd];
#pragma unroll
    for (int j = 0; j < Nd; ++j) h[j] = 0.f;
    float S = 0.f;

    const float4 wcv = *reinterpret_cast<const float4*>(&cw[(size_t)e * Kd]);
    const int i0 = (c == 0) ? 1 : 0;
    float w0 = __half2float(xs[(i0 + 0) * 128 + tid]);
    float w1 = __half2float(xs[(i0 + 1) * 128 + tid]);
    float w2 = __half2float(xs[(i0 + 2) * 128 + tid]);
    float w3 = __half2float(xs[(i0 + 3) * 128 + tid]);
    float pu = __half2float(__float2half_rn(
        silu_f(wcv.x * w0 + wcv.y * w1 + wcv.z * w2 + wcv.w * w3)));

    const size_t ubase = (size_t)b * Ld * Ed + (size_t)l0 * Ed + e;
    for (int t = 0; t < CLs; ++t) {
        const float pd = __half2float(dts[t * 128 + tid]);
        S += pd;
        const float em1 = expm1_small(pd * A0);
        float ej[Nd];
        pow_chain16(em1, 1.f + em1, ej);
        const float puA = pu * invA0;
#pragma unroll
        for (int j = 0; j < Nd; ++j) {
            const float rj = 1.f / (float)(j + 1);   // compile-time immediate
            const float m = ej[j] * rj;
            const float tt = fmaf(m, puA, h[j]);
            h[j] = fmaf(ej[j], h[j], tt);
        }
        float ucur;
        if (c == 0 && t == 0) {
            ucur = pu;                      // index 0 reused
        } else {
            w0 = w1; w1 = w2; w2 = w3;
            w3 = __half2float(xs[(t + 4) * 128 + tid]);
            ucur = __half2float(__float2half_rn(
                silu_f(wcv.x * w0 + wcv.y * w1 + wcv.z * w2 + wcv.w * w3)));
        }
        s_uh[ubase + (size_t)t * Ed] = __float2half_rn(ucur);
        pu = ucur;
    }
    const size_t ho = ((size_t)(b * NCH + c) * Nd) * Ed + e;
    const float Q = __expf(S * A0);
    float Pv = Q;
#pragma unroll
    for (int j = 0; j < Nd; ++j) {
        g_hend[ho + (size_t)j * Ed] = h[j];
        g_P[ho + (size_t)j * Ed] = Pv;
        Pv *= Q;
    }
}

// ---------------- scan phase B: combine chunk carries (coalesced) ------------------
__global__ __launch_bounds__(256)
void scan_phaseB()
{
    const int gid = blockIdx.x * 256 + threadIdx.x;    // 0 .. Bd*Nd*Ed-1
    const int b = gid >> 14;                           // Nd*Ed = 16384
    const int rem = gid & 16383;                       // n*Ed + e
    float h = 0.f;
    size_t idx = ((size_t)b * NCH * Nd) * Ed + rem;
    const size_t stride = (size_t)Nd * Ed;
#pragma unroll 4
    for (int c = 0; c < NCH; ++c) {
        g_hcarry[idx] = h;
        h = fmaf(g_P[idx], h, g_hend[idx]);
        idx += stride;
    }
}

// ---------------- scan phase C: SMEM-staged rescan + y + gate ----------------------
__global__ __launch_bounds__(128, 8)
void scan_phaseC(const float* __restrict__ A_log, const float* __restrict__ Dv)
{
    __shared__ __align__(16) __half dts[(CLs + 1) * 128];
    __shared__ __align__(16) __half us[(CLs + 1) * 128];
    __shared__ __align__(16) __half zs[CLs * 128];     // silu(z) staged
    __shared__ float Cs[CLs][Nd];

    const int tid = threadIdx.x;
    const int e0 = blockIdx.x * 128;
    const int e = e0 + tid;
    const int c = blockIdx.y, b = blockIdx.z;
    const int l0 = c * CLs;
    const size_t tok0 = (size_t)b * Ld + l0;

    {
        const uint32_t sd = (uint32_t)__cvta_generic_to_shared(dts);
        const uint32_t su = (uint32_t)__cvta_generic_to_shared(us);
        const uint32_t sz = (uint32_t)__cvta_generic_to_shared(zs);
        const uint32_t sc = (uint32_t)__cvta_generic_to_shared(Cs);
        const __half* db = g_dt16 + (size_t)b * Ld * Ed + e0;
        const __half* ub = s_uh   + (size_t)b * Ld * Ed + e0;
        const __half* zb = s_zh   + (size_t)b * Ld * Ed + e0;
#pragma unroll
        for (int it = 0; it < 5; ++it) {
            const int q = tid + it * 128;
            if (q < (CLs + 1) * 16) {
                const int row = q >> 4, cir = q & 15;
                int g = l0 - 1 + row;
                if (g < 0) g = 0;
                cp16(sd + (uint32_t)(row * 256 + cir * 16),
                     db + (size_t)g * Ed + cir * 8, 16);
                cp16(su + (uint32_t)(row * 256 + cir * 16),
                     ub + (size_t)g * Ed + cir * 8, 16);
            }
        }
#pragma unroll
        for (int it = 0; it < 4; ++it) {
            const int q = tid + it * 128;            // CLs*16 = 512 chunks
            const int row = q >> 4, cir = q & 15;
            cp16(sz + (uint32_t)(row * 256 + cir * 16),
                 zb + (size_t)(l0 + row) * Ed + cir * 8, 16);
        }
        // C: 32x16 fp32 = 2048B = 128 chunks
        cp16(sc + (uint32_t)(tid * 16), g_C + tok0 * Nd + tid * 4, 16);
        asm volatile("cp.async.commit_group;" ::: "memory");
        asm volatile("cp.async.wait_group 0;" ::: "memory");
        __syncthreads();
    }

    const float dve = Dv[e];
    const float A0 = g_A0[e];
    if (A0 == 0.f) { scanC_generic(A_log, dve, Cs, e, c, b); return; }
    const float invA0 = 1.f / A0;

    float h[Nd];
    const size_t ho = ((size_t)(b * NCH + c) * Nd) * Ed + e;
#pragma unroll
    for (int j = 0; j < Nd; ++j) h[j] = g_hcarry[ho + (size_t)j * Ed];

    const size_t gbase = tok0 * Ed + e;
    for (int t = 0; t < CLs; ++t) {
        const float pd = __half2float(dts[t * 128 + tid]);
        const float pu = __half2float(us[t * 128 + tid]);
        const float em1 = expm1_small(pd * A0);
        float ej[Nd];
        pow_chain16(em1, 1.f + em1, ej);
        const float puA = pu * invA0;
        float y0 = 0.f, y1 = 0.f, y2 = 0.f, y3 = 0.f;
#pragma unroll
        for (int j = 0; j < Nd; j += 4) {
            {
                const float rj = 1.f / (float)(j + 1);
                const float m = ej[j] * rj;
                const float tt = fmaf(m, puA, h[j]);
                h[j] = fmaf(ej[j], h[j], tt);
                y0 = fmaf(Cs[t][j], h[j], y0);
            }
            {
                const float rj = 1.f / (float)(j + 2);
                const float m = ej[j + 1] * rj;
                const float tt = fmaf(m, puA, h[j + 1]);
                h[j + 1] = fmaf(ej[j + 1], h[j + 1], tt);
                y1 = fmaf(Cs[t][j + 1], h[j + 1], y1);
            }
            {
                const float rj = 1.f / (float)(j + 3);
                const float m = ej[j + 2] * rj;
                const float tt = fmaf(m, puA, h[j + 2]);
                h[j + 2] = fmaf(ej[j + 2], h[j + 2], tt);
                y2 = fmaf(Cs[t][j + 2], h[j + 2], y2);
            }
            {
                const float rj = 1.f / (float)(j + 4);
                const float m = ej[j + 3] * rj;
                const float tt = fmaf(m, puA, h[j + 3]);
                h[j + 3] = fmaf(ej[j + 3], h[j + 3], tt);
                y3 = fmaf(Cs[t][j + 3], h[j + 3], y3);
            }
        }
        const float y = (y0 + y1) + (y2 + y3);
        const float u_cur = __half2float(us[(t + 1) * 128 + tid]);
        const float zs_cur = __half2float(zs[t * 128 + tid]);   // silu(z) precomputed
        const float ys = fmaf(u_cur, dve, y);
        s_gh[gbase + (size_t)t * Ed] = __float2half_rn(ys * zs_cur);
    }
}

// ---------------- host launcher ----------------
extern "C" void kernel_launch(void* const* d_in, const int* in_sizes, int n_in,
                              void* d_out, int out_size)
{
    const float* x     = (const float*)d_in[0];
    const float* W_z   = (const float*)d_in[1];
    const float* W_p   = (const float*)d_in[2];
    const float* cw    = (const float*)d_in[3];
    const float* W_dt  = (const float*)d_in[4];
    const float* b_dt  = (const float*)d_in[5];
    const float* A_log = (const float*)d_in[6];
    const float* Dv    = (const float*)d_in[7];
    const float* W_o   = (const float*)d_in[8];
    float* out = (float*)d_out;

    float* Cc;
    __half *dt16;
    cudaGetSymbolAddress((void**)&Cc,   g_C);
    cudaGetSymbolAddress((void**)&dt16, g_dt16);

    __half *xh, *zh, *gh, *ph, *wzh, *wph, *wdh, *woh;
    cudaGetSymbolAddress((void**)&xh, s_xh);
    cudaGetSymbolAddress((void**)&zh, s_zh);
    cudaGetSymbolAddress((void**)&gh, s_gh);
    cudaGetSymbolAddress((void**)&ph, s_ph);
    cudaGetSymbolAddress((void**)&wzh, s_wzh);
    cudaGetSymbolAddress((void**)&wph, s_wph);
    cudaGetSymbolAddress((void**)&wdh, s_wdh);
    cudaGetSymbolAddress((void**)&woh, s_woh);

    cudaFuncSetAttribute(gemm_zp,     cudaFuncAttributeMaxDynamicSharedMemorySize, GSM);
    cudaFuncSetAttribute(gemm_gen<0>, cudaFuncAttributeMaxDynamicSharedMemorySize, GSM);
    cudaFuncSetAttribute(gemm_gen<1>, cudaFuncAttributeMaxDynamicSharedMemorySize, GSM);

    dim3 blk(256);

    cast_all_kernel<<<(CNA + 255) / 256, blk>>>(x, W_z, W_p, W_dt, W_o, A_log);

    gemm_zp<<<dim3(9, Md / 128), blk, GSM>>>(xh, wzh, wph, zh, Cc, ph);
    gemm_gen<1><<<dim3(Ed / 128, Md / 128), blk, GSM>>>(ph, Pd, wdh, Rd,
                                                        dt16, Ed, Rd, b_dt);
    scan_phaseA<<<dim3(Ed / 128, NCH, Bd), dim3(128)>>>(A_log, cw);
    scan_phaseB<<<(Bd * Ed * Nd) / 256, blk>>>();
    scan_phaseC<<<dim3(Ed / 128, NCH, Bd), dim3(128)>>>(A_log, Dv);
    gemm_gen<0><<<dim3(Ed / 128, Md / 128), blk, GSM>>>(gh, Ed, woh, Ed,
                                                        out, Ed, Ed, nullptr);
}